// round 14
// baseline (speedup 1.0000x reference)
#include <cuda_runtime.h>
#include <cuda_fp16.h>
#include <cstdint>

#define NN 50000
#define EE 800000
#define GG 128
#define HH 128
#define LL 3
#define KK 3
#define EPSF 1e-5f
#define SCAN_B 256
#define NBLK ((NN + SCAN_B - 1) / SCAN_B)   // 196
#define NTILE ((NN + 127) / 128)            // 391

// ---------------- scratch (static device globals; no allocation) ----------------
__device__ __half g_h [NN*HH];   // features; cheb writes raw output here in place
__device__ __half g_t1[NN*HH];
__device__ float g_w0p[LL*HH*HH]; // W0 - W2 per layer
__device__ int   g_ecol[EE];
__device__ float g_ew [EE];
__device__ int   g_degi[NN];
__device__ float g_dinv[NN];
__device__ int   g_cnt[NN];
__device__ int   g_incl[NN];
__device__ int   g_bsum[SCAN_B];
__device__ int   g_bscan[SCAN_B];
__device__ int   g_rowptr[NN+1];
__device__ int   g_cur[NN];
__device__ float g_bnsum[LL*HH];
__device__ float g_bnsq [LL*HH];
__device__ double g_reg;
__device__ float g_gsum[GG*HH];
__device__ float g_gcnt[GG];

// ================= helpers =================
__device__ __forceinline__ uint32_t smem_u32(const void* p) {
    uint32_t a;
    asm("{ .reg .u64 t; cvta.to.shared.u64 t, %1; cvt.u32.u64 %0, t; }"
        : "=r"(a) : "l"(p));
    return a;
}

__device__ __forceinline__ float4 h2f4(uint2 u) {
    __half2 a = *(__half2*)&u.x, b = *(__half2*)&u.y;
    float2 fa = __half22float2(a), fb = __half22float2(b);
    return make_float4(fa.x, fa.y, fb.x, fb.y);
}
__device__ __forceinline__ uint2 f2h4(float4 v) {
    __half2 a = __floats2half2_rn(v.x, v.y);
    __half2 b = __floats2half2_rn(v.z, v.w);
    uint2 u;
    u.x = *(uint32_t*)&a;
    u.y = *(uint32_t*)&b;
    return u;
}

// D += A(16x8,row) * B(8x8,col)  tf32 inputs (raw fp32 bits), f32 accum
__device__ __forceinline__ void mma_tf32(float* d, const uint32_t* a, const uint32_t* b) {
    asm volatile(
        "mma.sync.aligned.m16n8k8.row.col.f32.tf32.tf32.f32 "
        "{%0,%1,%2,%3}, {%4,%5,%6,%7}, {%8,%9}, {%0,%1,%2,%3};"
        : "+f"(d[0]), "+f"(d[1]), "+f"(d[2]), "+f"(d[3])
        : "r"(a[0]), "r"(a[1]), "r"(a[2]), "r"(a[3]), "r"(b[0]), "r"(b[1]));
}

__device__ __forceinline__ void cp16(uint32_t dst, const void* src, bool pred) {
    int sz = pred ? 16 : 0;
    asm volatile("cp.async.cg.shared.global [%0], [%1], 16, %2;"
                 :: "r"(dst), "l"(src), "r"(sz));
}
#define CP_COMMIT() asm volatile("cp.async.commit_group;" ::: "memory")
#define CP_WAIT1()  asm volatile("cp.async.wait_group 1;" ::: "memory")
#define CP_WAIT0()  asm volatile("cp.async.wait_group 0;" ::: "memory")

// smem layout (uint32 units)
#define AS_PITCH 36
#define BS_PITCH 132
#define ST_PITCH 129
#define OFF_AS0  0
#define OFF_AS1  4608
#define OFF_BS0  9216
#define OFF_BS1  13440
#define OFF_STAGE 0
#define OFF_EXTRA 17664
#define OFF_T2   (OFF_EXTRA + 768)           // 128 rows x 32 uint2 (fp16 tile)
#define SMEM_U32_E (OFF_EXTRA + 768)
#define SMEM_DYN_E (SMEM_U32_E*4)            // embed: ~73.7 KB
#define SMEM_U32_C (OFF_T2 + 128*64)
#define SMEM_DYN_C (SMEM_U32_C*4)            // cheb: ~106.5 KB

// async-load fp32 A chunk [128 x 32] into As buf (embed only; x is fp32)
__device__ __forceinline__ void load_A_async(
    uint32_t sbase, int bufoff, const float* __restrict__ src, int row0, int kc)
{
    const float4* s4 = (const float4*)src;
    #pragma unroll
    for (int it = 0; it < 4; it++) {
        int idx = it * 256 + threadIdx.x;
        int r = idx >> 3, c4 = idx & 7;
        const float4* gp = s4 + (size_t)(row0 + r) * 32 + kc * 8 + c4;
        uint32_t dst = sbase + (bufoff + r * AS_PITCH + c4 * 4) * 4;
        cp16(dst, gp, row0 + r < NN);
    }
}

// async-load fp32 B chunk [32 k x 128 n] into Bs buf
__device__ __forceinline__ void load_B_async(
    uint32_t sbase, int bufoff, const float* __restrict__ W, int kc)
{
    const float4* s4 = (const float4*)W;
    #pragma unroll
    for (int it = 0; it < 4; it++) {
        int idx = it * 256 + threadIdx.x;
        int r = idx >> 5, c4 = idx & 31;
        const float4* gp = s4 + (size_t)(kc * 32 + r) * 32 + c4;
        uint32_t dst = sbase + (bufoff + r * BS_PITCH + c4 * 4) * 4;
        cp16(dst, gp, true);
    }
}

// fp16 A chunk: LDG into regs (2 x uint4 = 16 halves per thread)
__device__ __forceinline__ void ldg_A16(
    uint4* r, const __half* __restrict__ src, int row0, int kc)
{
    #pragma unroll
    for (int it = 0; it < 2; it++) {
        int idx = it * 256 + threadIdx.x;
        int rr = idx >> 2, c8 = idx & 3;
        if (row0 + rr < NN)
            r[it] = ((const uint4*)src)[(size_t)(row0 + rr) * 16 + kc * 4 + c8];
        else
            r[it] = make_uint4(0u, 0u, 0u, 0u);
    }
}

// convert regs -> fp32 bits into As buf
__device__ __forceinline__ void sts_A16(uint32_t* As, const uint4* r)
{
    #pragma unroll
    for (int it = 0; it < 2; it++) {
        int idx = it * 256 + threadIdx.x;
        int rr = idx >> 2, c8 = idx & 3;
        uint32_t* p = As + rr * AS_PITCH + c8 * 8;
        const uint32_t* w = (const uint32_t*)&r[it];
        #pragma unroll
        for (int j = 0; j < 4; j++) {
            __half2 h = *(__half2*)&w[j];
            float2 f = __half22float2(h);
            p[j * 2 + 0] = __float_as_uint(f.x);
            p[j * 2 + 1] = __float_as_uint(f.y);
        }
    }
}

// convert smem T2 tile chunk kc -> fp32 bits into As buf
__device__ __forceinline__ void sts_A16_T2(uint32_t* As, const uint2* T2s, int kc)
{
    #pragma unroll
    for (int it = 0; it < 2; it++) {
        int idx = it * 256 + threadIdx.x;
        int rr = idx >> 2, c8 = idx & 3;
        uint32_t* p = As + rr * AS_PITCH + c8 * 8;
        uint2 u0 = T2s[rr * 32 + kc * 8 + c8 * 2];
        uint2 u1 = T2s[rr * 32 + kc * 8 + c8 * 2 + 1];
        uint32_t w[4] = { u0.x, u0.y, u1.x, u1.y };
        #pragma unroll
        for (int j = 0; j < 4; j++) {
            __half2 h = *(__half2*)&w[j];
            float2 f = __half22float2(h);
            p[j * 2 + 0] = __float_as_uint(f.x);
            p[j * 2 + 1] = __float_as_uint(f.y);
        }
    }
}

// one 32-wide K chunk of MMAs
__device__ __forceinline__ void mma_chunk(
    const uint32_t* As, const uint32_t* Bs,
    float acc[2][8][4], int m0, int n0, int g, int t)
{
    #pragma unroll
    for (int ks = 0; ks < 4; ks++) {
        int k0 = ks * 8;
        uint32_t a[2][4];
        #pragma unroll
        for (int mf = 0; mf < 2; mf++) {
            int r = m0 + mf * 16 + g;
            a[mf][0] = As[r * AS_PITCH + k0 + t];
            a[mf][1] = As[(r + 8) * AS_PITCH + k0 + t];
            a[mf][2] = As[r * AS_PITCH + k0 + t + 4];
            a[mf][3] = As[(r + 8) * AS_PITCH + k0 + t + 4];
        }
        #pragma unroll
        for (int nf = 0; nf < 8; nf++) {
            int c = n0 + nf * 8 + g;
            uint32_t b[2];
            b[0] = Bs[(k0 + t) * BS_PITCH + c];
            b[1] = Bs[(k0 + t + 4) * BS_PITCH + c];
            mma_tf32(acc[0][nf], a[0], b);
            mma_tf32(acc[1][nf], a[1], b);
        }
    }
}

__device__ __forceinline__ void acc_to_stage(
    float* stage, const float* biasS, float acc[2][8][4],
    int m0, int n0, int g, int t)
{
    #pragma unroll
    for (int mf = 0; mf < 2; mf++) {
        #pragma unroll
        for (int nf = 0; nf < 8; nf++) {
            int c = n0 + nf * 8 + 2 * t;
            int r = m0 + mf * 16 + g;
            stage[r * ST_PITCH + c]           = acc[mf][nf][0] + biasS[c];
            stage[r * ST_PITCH + c + 1]       = acc[mf][nf][1] + biasS[c + 1];
            stage[(r + 8) * ST_PITCH + c]     = acc[mf][nf][2] + biasS[c];
            stage[(r + 8) * ST_PITCH + c + 1] = acc[mf][nf][3] + biasS[c + 1];
        }
    }
}

// x4-unrolled gather over [lo,hi): acc += w*SRC[col]; optional reg vs hd
template <bool REG>
__device__ __forceinline__ void gather_range(
    const uint2* __restrict__ SRC, int lo, int hi, int lane,
    float4 hd, float4& acc, float& ss)
{
    int e = lo;
    for (; e + 4 <= hi; e += 4) {
        int s0 = g_ecol[e],   s1 = g_ecol[e+1];
        int s2 = g_ecol[e+2], s3 = g_ecol[e+3];
        float w0 = g_ew[e],   w1 = g_ew[e+1];
        float w2 = g_ew[e+2], w3 = g_ew[e+3];
        float4 h0 = h2f4(SRC[(size_t)s0 * 32 + lane]);
        float4 h1 = h2f4(SRC[(size_t)s1 * 32 + lane]);
        float4 h2 = h2f4(SRC[(size_t)s2 * 32 + lane]);
        float4 h3 = h2f4(SRC[(size_t)s3 * 32 + lane]);
        acc.x = fmaf(w0,h0.x,acc.x); acc.y = fmaf(w0,h0.y,acc.y);
        acc.z = fmaf(w0,h0.z,acc.z); acc.w = fmaf(w0,h0.w,acc.w);
        if (REG) {
            float dx=h0.x-hd.x, dy=h0.y-hd.y, dz=h0.z-hd.z, dw=h0.w-hd.w;
            ss=fmaf(dx,dx,ss); ss=fmaf(dy,dy,ss); ss=fmaf(dz,dz,ss); ss=fmaf(dw,dw,ss);
        }
        acc.x = fmaf(w1,h1.x,acc.x); acc.y = fmaf(w1,h1.y,acc.y);
        acc.z = fmaf(w1,h1.z,acc.z); acc.w = fmaf(w1,h1.w,acc.w);
        if (REG) {
            float dx=h1.x-hd.x, dy=h1.y-hd.y, dz=h1.z-hd.z, dw=h1.w-hd.w;
            ss=fmaf(dx,dx,ss); ss=fmaf(dy,dy,ss); ss=fmaf(dz,dz,ss); ss=fmaf(dw,dw,ss);
        }
        acc.x = fmaf(w2,h2.x,acc.x); acc.y = fmaf(w2,h2.y,acc.y);
        acc.z = fmaf(w2,h2.z,acc.z); acc.w = fmaf(w2,h2.w,acc.w);
        if (REG) {
            float dx=h2.x-hd.x, dy=h2.y-hd.y, dz=h2.z-hd.z, dw=h2.w-hd.w;
            ss=fmaf(dx,dx,ss); ss=fmaf(dy,dy,ss); ss=fmaf(dz,dz,ss); ss=fmaf(dw,dw,ss);
        }
        acc.x = fmaf(w3,h3.x,acc.x); acc.y = fmaf(w3,h3.y,acc.y);
        acc.z = fmaf(w3,h3.z,acc.z); acc.w = fmaf(w3,h3.w,acc.w);
        if (REG) {
            float dx=h3.x-hd.x, dy=h3.y-hd.y, dz=h3.z-hd.z, dw=h3.w-hd.w;
            ss=fmaf(dx,dx,ss); ss=fmaf(dy,dy,ss); ss=fmaf(dz,dz,ss); ss=fmaf(dw,dw,ss);
        }
    }
    for (; e < hi; e++) {
        int s = g_ecol[e];
        float w = g_ew[e];
        float4 hv = h2f4(SRC[(size_t)s * 32 + lane]);
        acc.x = fmaf(w,hv.x,acc.x); acc.y = fmaf(w,hv.y,acc.y);
        acc.z = fmaf(w,hv.z,acc.z); acc.w = fmaf(w,hv.w,acc.w);
        if (REG) {
            float dx=hv.x-hd.x, dy=hv.y-hd.y, dz=hv.z-hd.z, dw=hv.w-hd.w;
            ss=fmaf(dx,dx,ss); ss=fmaf(dy,dy,ss); ss=fmaf(dz,dz,ss); ss=fmaf(dw,dw,ss);
        }
    }
}

// ---------------- init ----------------
__global__ void k_init() {
    int i = blockIdx.x * blockDim.x + threadIdx.x;
    if (i < NN)    { g_degi[i] = 0; g_cnt[i] = 0; g_cur[i] = 0; }
    if (i < GG*HH)   g_gsum[i] = 0.f;
    if (i < GG)      g_gcnt[i] = 0.f;
    if (i < LL*HH) { g_bnsum[i] = 0.f; g_bnsq[i] = 0.f; }
    if (i == 0)      g_reg = 0.0;
}

// ---------------- edge prep: degree counts only ----------------
__global__ void k_edge_prep(const int* __restrict__ ei) {
    int e = blockIdx.x * blockDim.x + threadIdx.x;
    if (e >= EE) return;
    atomicAdd(&g_degi[ei[e]], 1);
    atomicAdd(&g_cnt[ei[EE + e]], 1);
}

// ---------------- scan (scan1 also computes dinv) ----------------
__global__ void k_scan1() {
    __shared__ int sm[SCAN_B];
    int i = blockIdx.x * SCAN_B + threadIdx.x;
    if (i < NN) {
        int d = g_degi[i];
        g_dinv[i] = d > 0 ? rsqrtf((float)d) : 0.f;
    }
    int v = (i < NN) ? g_cnt[i] : 0;
    sm[threadIdx.x] = v;
    __syncthreads();
    #pragma unroll
    for (int off = 1; off < SCAN_B; off <<= 1) {
        int t = (threadIdx.x >= off) ? sm[threadIdx.x - off] : 0;
        __syncthreads();
        sm[threadIdx.x] += t;
        __syncthreads();
    }
    if (i < NN) g_incl[i] = sm[threadIdx.x];
    if (threadIdx.x == SCAN_B - 1) g_bsum[blockIdx.x] = sm[threadIdx.x];
}

__global__ void k_scan2() {
    __shared__ int sm[SCAN_B];
    int t0 = threadIdx.x;
    sm[t0] = (t0 < NBLK) ? g_bsum[t0] : 0;
    __syncthreads();
    #pragma unroll
    for (int off = 1; off < SCAN_B; off <<= 1) {
        int t = (t0 >= off) ? sm[t0 - off] : 0;
        __syncthreads();
        sm[t0] += t;
        __syncthreads();
    }
    g_bscan[t0] = sm[t0];
}

__global__ void k_scan3() {
    int i = blockIdx.x * SCAN_B + threadIdx.x;
    if (i < NN) {
        int off = (blockIdx.x > 0) ? g_bscan[blockIdx.x - 1] : 0;
        g_rowptr[i] = g_incl[i] - g_cnt[i] + off;
    }
    if (i == 0) g_rowptr[NN] = EE;
}

__global__ void k_scatter(const int* __restrict__ ei) {
    int e = blockIdx.x * blockDim.x + threadIdx.x;
    if (e >= EE) return;
    int s = ei[e], d = ei[EE + e];
    int pos = g_rowptr[d] + atomicAdd(&g_cur[d], 1);
    g_ecol[pos] = s;
    g_ew[pos] = -g_dinv[s] * g_dinv[d];
}

// ---------------- W0' = W0 - W2 per layer ----------------
__global__ void k_wprep(const float* __restrict__ cheb_w) {
    int i = blockIdx.x * blockDim.x + threadIdx.x;
    int l = i / (HH * HH);
    int r = i % (HH * HH);
    g_w0p[i] = cheb_w[(size_t)l * KK * HH * HH + r]
             - cheb_w[(size_t)l * KK * HH * HH + 2 * HH * HH + r];
}

// ---------------- embed: x@W + b -> LayerNorm -> ReLU  (pipelined tf32 mma) ----------------
__global__ void __launch_bounds__(256) k_embed_mma(
    const float* __restrict__ x, const float* __restrict__ W,
    const float* __restrict__ b_in, const float* __restrict__ lng,
    const float* __restrict__ lnb)
{
    extern __shared__ uint32_t smem[];
    uint32_t sbase = smem_u32(smem);
    float* stage = (float*)(smem + OFF_STAGE);
    float* biasS = (float*)(smem + OFF_EXTRA);
    float* lngS  = biasS + 128;
    float* lnbS  = lngS + 128;
    float* muS   = lnbS + 128;
    float* rsS   = muS + 128;

    int tid = threadIdx.x;
    int lane = tid & 31, warp = tid >> 5;
    int g = lane >> 2, t = lane & 3;
    int m0 = (warp >> 1) * 32, n0 = (warp & 1) * 64;
    int row0 = blockIdx.x * 128;

    if (tid < 128) {
        biasS[tid] = b_in[tid];
        lngS[tid]  = lng[tid];
        lnbS[tid]  = lnb[tid];
    }

    float acc[2][8][4];
    #pragma unroll
    for (int i = 0; i < 2; i++)
        #pragma unroll
        for (int j = 0; j < 8; j++)
            { acc[i][j][0]=0.f; acc[i][j][1]=0.f; acc[i][j][2]=0.f; acc[i][j][3]=0.f; }

    const int NCH = 4;
    load_A_async(sbase, OFF_AS0, x, row0, 0);
    load_B_async(sbase, OFF_BS0, W, 0);
    CP_COMMIT();

    for (int i = 0; i < NCH; i++) {
        int abuf = (i & 1) ? OFF_AS1 : OFF_AS0;
        int bbuf = (i & 1) ? OFF_BS1 : OFF_BS0;
        if (i + 1 < NCH) {
            int a2 = ((i + 1) & 1) ? OFF_AS1 : OFF_AS0;
            int b2 = ((i + 1) & 1) ? OFF_BS1 : OFF_BS0;
            load_A_async(sbase, a2, x, row0, i + 1);
            load_B_async(sbase, b2, W, i + 1);
            CP_COMMIT();
            CP_WAIT1();
        } else {
            CP_WAIT0();
        }
        __syncthreads();
        mma_chunk(smem + abuf, smem + bbuf, acc, m0, n0, g, t);
        __syncthreads();
    }

    acc_to_stage(stage, biasS, acc, m0, n0, g, t);
    __syncthreads();

    if (tid < 128) {
        float s = 0.f, sq = 0.f;
        #pragma unroll 8
        for (int c = 0; c < HH; c++) {
            float v = stage[tid * ST_PITCH + c];
            s += v; sq = fmaf(v, v, sq);
        }
        float mu  = s * (1.f / HH);
        float var = sq * (1.f / HH) - mu * mu;
        muS[tid] = mu;
        rsS[tid] = rsqrtf(var + EPSF);
    }
    __syncthreads();

    for (int idx = tid; idx < 128 * HH; idx += 256) {
        int r = idx >> 7, c = idx & 127;
        if (row0 + r < NN) {
            float v = stage[r * ST_PITCH + c];
            v = (v - muS[r]) * rsS[r] * lngS[c] + lnbS[c];
            g_h[(size_t)(row0 + r) * HH + c] = __float2half(fmaxf(v, 0.f));
        }
    }
}

// ---------------- fused cheb: t2 tile gathered in-block; g_h updated in place ----------------
// g_h = h@(W0-W2) + t1@W1 + (2 L_hat t1)@W2 + b ; BN stats accumulated
__global__ void __launch_bounds__(256) k_cheb_mma(
    int l, const float* __restrict__ W, const float* __restrict__ bias)
{
    extern __shared__ uint32_t smem[];
    uint32_t sbase = smem_u32(smem);
    float* stage = (float*)(smem + OFF_STAGE);
    float* biasS = (float*)(smem + OFF_EXTRA);
    float* sCs   = biasS + 128;
    float* sCq   = sCs + 128;
    uint2* T2s   = (uint2*)(smem + OFF_T2);

    int tid = threadIdx.x;
    int lane = tid & 31, warp = tid >> 5;
    int g = lane >> 2, t = lane & 3;
    int m0 = (warp >> 1) * 32, n0 = (warp & 1) * 64;
    int row0 = blockIdx.x * 128;

    const float* W0p = g_w0p + (size_t)l * HH * HH;

    if (tid < 128) { biasS[tid] = bias[tid]; sCs[tid] = 0.f; sCq[tid] = 0.f; }

    float acc[2][8][4];
    #pragma unroll
    for (int i = 0; i < 2; i++)
        #pragma unroll
        for (int j = 0; j < 8; j++)
            { acc[i][j][0]=0.f; acc[i][j][1]=0.f; acc[i][j][2]=0.f; acc[i][j][3]=0.f; }

    // kick off chunk-0 loads so they overlap the t2 gather below
    uint4 aregs[2], anext[2];
    ldg_A16(aregs, g_h, row0, 0);
    load_B_async(sbase, OFF_BS0, W0p, 0);
    CP_COMMIT();

    // gather t2 tile = 2 * L_hat t1 for this block's 128 rows into smem
    {
        const uint2* T1g = (const uint2*)g_t1;
        for (int r = warp; r < 128; r += 8) {
            int node = row0 + r;
            float4 gacc = make_float4(0.f, 0.f, 0.f, 0.f);
            float dummy_ss = 0.f;
            if (node < NN) {
                int beg = g_rowptr[node], end = g_rowptr[node + 1];
                gather_range<false>(T1g, beg, end, lane, gacc, gacc, dummy_ss);
            }
            T2s[r * 32 + lane] = f2h4(make_float4(
                2.f * gacc.x, 2.f * gacc.y, 2.f * gacc.z, 2.f * gacc.w));
        }
    }
    __syncthreads();   // T2 visible; also covers biasS/sCs init

    const __half* Asrc[2] = { g_h, g_t1 };
    const int NCH = 12;

    for (int i = 0; i < NCH; i++) {
        int abuf = (i & 1) ? OFF_AS1 : OFF_AS0;
        int bbuf = (i & 1) ? OFF_BS1 : OFF_BS0;
        if (i < 8) sts_A16(smem + abuf, aregs);
        else       sts_A16_T2(smem + abuf, T2s, i & 3);
        if (i + 1 < NCH) {
            int j = i + 1;
            const float* Wm = ((j >> 2) == 0) ? W0p : (W + (size_t)(j >> 2) * HH * HH);
            if (j < 8) ldg_A16(anext, Asrc[j >> 2], row0, j & 3);
            load_B_async(sbase, (j & 1) ? OFF_BS1 : OFF_BS0, Wm, j & 3);
            CP_COMMIT();
            CP_WAIT1();
        } else {
            CP_WAIT0();
        }
        __syncthreads();
        mma_chunk(smem + abuf, smem + bbuf, acc, m0, n0, g, t);
        __syncthreads();
        if (i + 1 < 8) {
            aregs[0] = anext[0];
            aregs[1] = anext[1];
        }
    }

    acc_to_stage(stage, biasS, acc, m0, n0, g, t);
    __syncthreads();

    {
        float ps = 0.f, pq = 0.f;
        int c = tid & 127;
        int rbase = tid >> 7;
        #pragma unroll 4
        for (int k = 0; k < 64; k++) {
            int r = rbase + k * 2;
            int row = row0 + r;
            if (row < NN) {
                float v = stage[r * ST_PITCH + c];
                g_h[(size_t)row * HH + c] = __float2half(v);
                ps += v; pq = fmaf(v, v, pq);
            }
        }
        atomicAdd(&sCs[c], ps);
        atomicAdd(&sCq[c], pq);
    }
    __syncthreads();
    if (tid < 128) {
        atomicAdd(&g_bnsum[l * HH + tid], sCs[tid]);
        atomicAdd(&g_bnsq[l * HH + tid],  sCq[tid]);
    }
}

// ---------------- CSR spmm #1: t1 = L_hat h; fused Dirichlet reg (R7 form) ----------------
__global__ void __launch_bounds__(256) k_spmm1() {
    __shared__ float blk_ss[8];
    int warp = blockIdx.x * 8 + (threadIdx.x >> 5);
    int lane = threadIdx.x & 31;
    const uint2* H = (const uint2*)g_h;
    float ss = 0.f;
    if (warp < NN) {
        int beg = g_rowptr[warp], end = g_rowptr[warp + 1];
        float4 hd = h2f4(H[(size_t)warp * 32 + lane]);
        float4 acc = make_float4(0.f, 0.f, 0.f, 0.f);
        gather_range<true>(H, beg, end, lane, hd, acc, ss);
        ((uint2*)g_t1)[(size_t)warp * 32 + lane] = f2h4(acc);
    }
    #pragma unroll
    for (int off = 16; off > 0; off >>= 1)
        ss += __shfl_xor_sync(0xffffffffu, ss, off);
    if (lane == 0) blk_ss[threadIdx.x >> 5] = ss;
    __syncthreads();
    if (threadIdx.x == 0) {
        double tot = 0.0;
        #pragma unroll
        for (int j = 0; j < 8; j++) tot += (double)blk_ss[j];
        atomicAdd(&g_reg, tot);
    }
}

// ---------------- fused: Dirichlet reg of final h + global mean pool (R7 form) ----------------
__global__ void __launch_bounds__(256) k_regpool(const int* __restrict__ batch) {
    __shared__ float blk_ss[8];
    int warp = blockIdx.x * 8 + (threadIdx.x >> 5);
    int lane = threadIdx.x & 31;
    const uint2* H = (const uint2*)g_h;
    float ss = 0.f;
    if (warp < NN) {
        int beg = g_rowptr[warp], end = g_rowptr[warp + 1];
        float4 hd = h2f4(H[(size_t)warp * 32 + lane]);
        float4 acc = make_float4(0.f, 0.f, 0.f, 0.f);  // discarded
        gather_range<true>(H, beg, end, lane, hd, acc, ss);
        int b = batch[warp];
        float* gp = &g_gsum[(size_t)b * HH + lane * 4];
        atomicAdd(gp + 0, hd.x);
        atomicAdd(gp + 1, hd.y);
        atomicAdd(gp + 2, hd.z);
        atomicAdd(gp + 3, hd.w);
        if (lane == 0) atomicAdd(&g_gcnt[b], 1.f);
    }
    #pragma unroll
    for (int off = 16; off > 0; off >>= 1)
        ss += __shfl_xor_sync(0xffffffffu, ss, off);
    if (lane == 0) blk_ss[threadIdx.x >> 5] = ss;
    __syncthreads();
    if (threadIdx.x == 0) {
        double tot = 0.0;
        #pragma unroll
        for (int j = 0; j < 8; j++) tot += (double)blk_ss[j];
        atomicAdd(&g_reg, tot);
    }
}

// ---------------- BN apply in place (scale/shift computed inline) ----------------
__global__ void k_bnapply(int l, const float* __restrict__ bng, const float* __restrict__ bnb) {
    int i = blockIdx.x * blockDim.x + threadIdx.x;
    int c4 = i & 31;
    float sc[4], sh[4];
    #pragma unroll
    for (int k = 0; k < 4; k++) {
        int c = c4 * 4 + k;
        float m = g_bnsum[l * HH + c] * (1.f / NN);
        float v = g_bnsq[l * HH + c] * (1.f / NN) - m * m;
        float s = bng[c] * rsqrtf(v + EPSF);
        sc[k] = s;
        sh[k] = bnb[c] - m * s;
    }
    float4 v = h2f4(((const uint2*)g_h)[i]);
    float4 o;
    o.x = fmaxf(fmaf(v.x, sc[0], sh[0]), 0.f);
    o.y = fmaxf(fmaf(v.y, sc[1], sh[1]), 0.f);
    o.z = fmaxf(fmaf(v.z, sc[2], sh[2]), 0.f);
    o.w = fmaxf(fmaf(v.w, sc[3], sh[3]), 0.f);
    ((uint2*)g_h)[i] = f2h4(o);
}

// ---------------- MLP head + output ----------------
__global__ void k_head(const float* __restrict__ w1, const float* __restrict__ b1,
                       const float* __restrict__ w2, const float* __restrict__ b2,
                       float* __restrict__ out, int out_size)
{
    __shared__ float gm[HH];
    __shared__ float zz[64];
    int g = blockIdx.x, t = threadIdx.x;
    float cnt = fmaxf(g_gcnt[g], 1.f);
    gm[t] = g_gsum[(size_t)g * HH + t] / cnt;
    __syncthreads();
    if (t < 64) {
        float a = b1[t];
        #pragma unroll 4
        for (int c = 0; c < HH; c++) a = fmaf(gm[c], w1[c * 64 + t], a);
        zz[t] = fmaxf(a, 0.f);
    }
    __syncthreads();
    if (t < 2) {
        float a = b2[t];
        #pragma unroll 4
        for (int k = 0; k < 64; k++) a = fmaf(zz[k], w2[k * 2 + t], a);
        out[g * 2 + t] = a;
    }
    if (g == 0 && t == 0 && out_size > 256)
        out[256] = (float)(g_reg / (4.0 * (double)EE));
}

// ---------------- launch ----------------
extern "C" void kernel_launch(void* const* d_in, const int* in_sizes, int n_in,
                              void* d_out, int out_size)
{
    const float* x      = (const float*)d_in[0];
    const float* w_in   = (const float*)d_in[1];
    const float* b_in   = (const float*)d_in[2];
    const float* ln_g   = (const float*)d_in[3];
    const float* ln_b   = (const float*)d_in[4];
    const float* cheb_w = (const float*)d_in[5];
    const float* cheb_b = (const float*)d_in[6];
    const float* bn_g   = (const float*)d_in[7];
    const float* bn_b   = (const float*)d_in[8];
    const float* w1     = (const float*)d_in[9];
    const float* b1     = (const float*)d_in[10];
    const float* w2     = (const float*)d_in[11];
    const float* b2     = (const float*)d_in[12];
    const int* ei       = (const int*)d_in[13];
    const int* batch    = (const int*)d_in[14];
    float* out = (float*)d_out;

    cudaFuncSetAttribute(k_embed_mma, cudaFuncAttributeMaxDynamicSharedMemorySize, SMEM_DYN_E);
    cudaFuncSetAttribute(k_cheb_mma,  cudaFuncAttributeMaxDynamicSharedMemorySize, SMEM_DYN_C);

    const int FB = NN * 32 / 256;            // 6250 (uint2 elements / 256)
    const int NODE_WARP_BLKS = (NN + 7) / 8; // 6250

    k_init<<<(NN + 255) / 256, 256>>>();
    k_edge_prep<<<EE / 256, 256>>>(ei);
    k_scan1<<<NBLK, SCAN_B>>>();             // + dinv
    k_scan2<<<1, SCAN_B>>>();
    k_scan3<<<NBLK, SCAN_B>>>();
    k_scatter<<<EE / 256, 256>>>(ei);
    k_wprep<<<(LL * HH * HH) / 256, 256>>>(cheb_w);

    k_embed_mma<<<NTILE, 256, SMEM_DYN_E>>>(x, w_in, b_in, ln_g, ln_b);

    for (int l = 0; l < LL; l++) {
        k_spmm1<<<NODE_WARP_BLKS, 256>>>();
        k_cheb_mma<<<NTILE, 256, SMEM_DYN_C>>>(l,
                                               cheb_w + (size_t)l * KK * HH * HH,
                                               cheb_b + (size_t)l * HH);
        k_bnapply<<<FB, 256>>>(l, bn_g + (size_t)l * HH, bn_b + (size_t)l * HH);
    }

    k_regpool<<<NODE_WARP_BLKS, 256>>>(batch);
    k_head<<<GG, HH>>>(w1, b1, w2, b2, out, out_size);
}

// round 15
// speedup vs baseline: 1.2260x; 1.2260x over previous
#include <cuda_runtime.h>
#include <cuda_fp16.h>
#include <cstdint>

#define NN 50000
#define EE 800000
#define GG 128
#define HH 128
#define LL 3
#define KK 3
#define EPSF 1e-5f
#define SCAN_B 256
#define NBLK ((NN + SCAN_B - 1) / SCAN_B)   // 196
#define NTILE ((NN + 127) / 128)            // 391

// ---------------- scratch (static device globals; no allocation) ----------------
__device__ __half g_h [NN*HH];
__device__ __half g_t1[NN*HH];
__device__ __half g_t2[NN*HH];
__device__ __half g_o [NN*HH];
__device__ int   g_src[EE];
__device__ int   g_dst[EE];
__device__ int   g_ecol[EE];
__device__ float g_ew [EE];
__device__ int   g_degi[NN];
__device__ float g_dinv[NN];
__device__ int   g_cnt[NN];
__device__ int   g_incl[NN];
__device__ int   g_bsum[SCAN_B];
__device__ int   g_bscan[SCAN_B];
__device__ int   g_rowptr[NN+1];
__device__ int   g_cur[NN];
__device__ float g_bnsum[HH];
__device__ float g_bnsq [HH];
__device__ float g_bnscale[HH];
__device__ float g_bnshift[HH];
__device__ double g_reg;
__device__ float g_gsum[GG*HH];
__device__ float g_gcnt[GG];

// ================= helpers =================
__device__ __forceinline__ uint32_t smem_u32(const void* p) {
    uint32_t a;
    asm("{ .reg .u64 t; cvta.to.shared.u64 t, %1; cvt.u32.u64 %0, t; }"
        : "=r"(a) : "l"(p));
    return a;
}

__device__ __forceinline__ float4 h2f4(uint2 u) {
    __half2 a = *(__half2*)&u.x, b = *(__half2*)&u.y;
    float2 fa = __half22float2(a), fb = __half22float2(b);
    return make_float4(fa.x, fa.y, fb.x, fb.y);
}
__device__ __forceinline__ uint2 f2h4(float4 v) {
    __half2 a = __floats2half2_rn(v.x, v.y);
    __half2 b = __floats2half2_rn(v.z, v.w);
    uint2 u;
    u.x = *(uint32_t*)&a;
    u.y = *(uint32_t*)&b;
    return u;
}

// D += A(16x8,row) * B(8x8,col)  tf32 inputs (raw fp32 bits), f32 accum
__device__ __forceinline__ void mma_tf32(float* d, const uint32_t* a, const uint32_t* b) {
    asm volatile(
        "mma.sync.aligned.m16n8k8.row.col.f32.tf32.tf32.f32 "
        "{%0,%1,%2,%3}, {%4,%5,%6,%7}, {%8,%9}, {%0,%1,%2,%3};"
        : "+f"(d[0]), "+f"(d[1]), "+f"(d[2]), "+f"(d[3])
        : "r"(a[0]), "r"(a[1]), "r"(a[2]), "r"(a[3]), "r"(b[0]), "r"(b[1]));
}

__device__ __forceinline__ void cp16(uint32_t dst, const void* src, bool pred) {
    int sz = pred ? 16 : 0;
    asm volatile("cp.async.cg.shared.global [%0], [%1], 16, %2;"
                 :: "r"(dst), "l"(src), "r"(sz));
}
#define CP_COMMIT() asm volatile("cp.async.commit_group;" ::: "memory")
#define CP_WAIT1()  asm volatile("cp.async.wait_group 1;" ::: "memory")
#define CP_WAIT0()  asm volatile("cp.async.wait_group 0;" ::: "memory")

// smem layout (uint32 units): double-buffered As/Bs; stage overlaps them
#define AS_PITCH 36
#define BS_PITCH 132
#define ST_PITCH 129
#define OFF_AS0  0
#define OFF_AS1  4608
#define OFF_BS0  9216
#define OFF_BS1  13440
#define OFF_STAGE 0
#define OFF_EXTRA 17664
#define SMEM_U32 (OFF_EXTRA + 128*6)
#define SMEM_DYN (SMEM_U32*4)

// async-load fp32 A chunk [128 x 32] into As buf (embed only; x is fp32)
__device__ __forceinline__ void load_A_async(
    uint32_t sbase, int bufoff, const float* __restrict__ src, int row0, int kc)
{
    const float4* s4 = (const float4*)src;
    #pragma unroll
    for (int it = 0; it < 4; it++) {
        int idx = it * 256 + threadIdx.x;
        int r = idx >> 3, c4 = idx & 7;
        const float4* gp = s4 + (size_t)(row0 + r) * 32 + kc * 8 + c4;
        uint32_t dst = sbase + (bufoff + r * AS_PITCH + c4 * 4) * 4;
        cp16(dst, gp, row0 + r < NN);
    }
}

// async-load fp32 B chunk [32 k x 128 n] into Bs buf
__device__ __forceinline__ void load_B_async(
    uint32_t sbase, int bufoff, const float* __restrict__ W, int kc)
{
    const float4* s4 = (const float4*)W;
    #pragma unroll
    for (int it = 0; it < 4; it++) {
        int idx = it * 256 + threadIdx.x;
        int r = idx >> 5, c4 = idx & 31;
        const float4* gp = s4 + (size_t)(kc * 32 + r) * 32 + c4;
        uint32_t dst = sbase + (bufoff + r * BS_PITCH + c4 * 4) * 4;
        cp16(dst, gp, true);
    }
}

// fp16 A chunk: LDG into regs (2 x uint4 = 16 halves per thread)
__device__ __forceinline__ void ldg_A16(
    uint4* r, const __half* __restrict__ src, int row0, int kc)
{
    #pragma unroll
    for (int it = 0; it < 2; it++) {
        int idx = it * 256 + threadIdx.x;
        int rr = idx >> 2, c8 = idx & 3;
        if (row0 + rr < NN)
            r[it] = ((const uint4*)src)[(size_t)(row0 + rr) * 16 + kc * 4 + c8];
        else
            r[it] = make_uint4(0u, 0u, 0u, 0u);
    }
}

// convert regs -> fp32 bits into As buf
__device__ __forceinline__ void sts_A16(uint32_t* As, const uint4* r)
{
    #pragma unroll
    for (int it = 0; it < 2; it++) {
        int idx = it * 256 + threadIdx.x;
        int rr = idx >> 2, c8 = idx & 3;
        uint32_t* p = As + rr * AS_PITCH + c8 * 8;
        const uint32_t* w = (const uint32_t*)&r[it];
        #pragma unroll
        for (int j = 0; j < 4; j++) {
            __half2 h = *(__half2*)&w[j];
            float2 f = __half22float2(h);
            p[j * 2 + 0] = __float_as_uint(f.x);
            p[j * 2 + 1] = __float_as_uint(f.y);
        }
    }
}

// one 32-wide K chunk of MMAs
__device__ __forceinline__ void mma_chunk(
    const uint32_t* As, const uint32_t* Bs,
    float acc[2][8][4], int m0, int n0, int g, int t)
{
    #pragma unroll
    for (int ks = 0; ks < 4; ks++) {
        int k0 = ks * 8;
        uint32_t a[2][4];
        #pragma unroll
        for (int mf = 0; mf < 2; mf++) {
            int r = m0 + mf * 16 + g;
            a[mf][0] = As[r * AS_PITCH + k0 + t];
            a[mf][1] = As[(r + 8) * AS_PITCH + k0 + t];
            a[mf][2] = As[r * AS_PITCH + k0 + t + 4];
            a[mf][3] = As[(r + 8) * AS_PITCH + k0 + t + 4];
        }
        #pragma unroll
        for (int nf = 0; nf < 8; nf++) {
            int c = n0 + nf * 8 + g;
            uint32_t b[2];
            b[0] = Bs[(k0 + t) * BS_PITCH + c];
            b[1] = Bs[(k0 + t + 4) * BS_PITCH + c];
            mma_tf32(acc[0][nf], a[0], b);
            mma_tf32(acc[1][nf], a[1], b);
        }
    }
}

__device__ __forceinline__ void acc_to_stage(
    float* stage, const float* biasS, float acc[2][8][4],
    int m0, int n0, int g, int t)
{
    #pragma unroll
    for (int mf = 0; mf < 2; mf++) {
        #pragma unroll
        for (int nf = 0; nf < 8; nf++) {
            int c = n0 + nf * 8 + 2 * t;
            int r = m0 + mf * 16 + g;
            stage[r * ST_PITCH + c]           = acc[mf][nf][0] + biasS[c];
            stage[r * ST_PITCH + c + 1]       = acc[mf][nf][1] + biasS[c + 1];
            stage[(r + 8) * ST_PITCH + c]     = acc[mf][nf][2] + biasS[c];
            stage[(r + 8) * ST_PITCH + c + 1] = acc[mf][nf][3] + biasS[c + 1];
        }
    }
}

// ---------------- init ----------------
__global__ void k_init() {
    int i = blockIdx.x * blockDim.x + threadIdx.x;
    if (i < NN)    { g_degi[i] = 0; g_cnt[i] = 0; g_cur[i] = 0; }
    if (i < GG*HH)   g_gsum[i] = 0.f;
    if (i < GG)      g_gcnt[i] = 0.f;
    if (i < HH)    { g_bnsum[i] = 0.f; g_bnsq[i] = 0.f; }
    if (i == 0)      g_reg = 0.0;
}

// ---------------- edge prep ----------------
__global__ void k_edge_prep(const int* __restrict__ ei) {
    int e = blockIdx.x * blockDim.x + threadIdx.x;
    if (e >= EE) return;
    int s = ei[e];
    int d = ei[EE + e];
    g_src[e] = s;
    g_dst[e] = d;
    atomicAdd(&g_degi[s], 1);
    atomicAdd(&g_cnt[d], 1);
}

__global__ void k_dinv() {
    int i = blockIdx.x * blockDim.x + threadIdx.x;
    if (i >= NN) return;
    int d = g_degi[i];
    g_dinv[i] = d > 0 ? rsqrtf((float)d) : 0.f;
}

// ---------------- scan ----------------
__global__ void k_scan1() {
    __shared__ int sm[SCAN_B];
    int i = blockIdx.x * SCAN_B + threadIdx.x;
    int v = (i < NN) ? g_cnt[i] : 0;
    sm[threadIdx.x] = v;
    __syncthreads();
    #pragma unroll
    for (int off = 1; off < SCAN_B; off <<= 1) {
        int t = (threadIdx.x >= off) ? sm[threadIdx.x - off] : 0;
        __syncthreads();
        sm[threadIdx.x] += t;
        __syncthreads();
    }
    if (i < NN) g_incl[i] = sm[threadIdx.x];
    if (threadIdx.x == SCAN_B - 1) g_bsum[blockIdx.x] = sm[threadIdx.x];
}

__global__ void k_scan2() {
    __shared__ int sm[SCAN_B];
    int t0 = threadIdx.x;
    sm[t0] = (t0 < NBLK) ? g_bsum[t0] : 0;
    __syncthreads();
    #pragma unroll
    for (int off = 1; off < SCAN_B; off <<= 1) {
        int t = (t0 >= off) ? sm[t0 - off] : 0;
        __syncthreads();
        sm[t0] += t;
        __syncthreads();
    }
    g_bscan[t0] = sm[t0];
}

__global__ void k_scan3() {
    int i = blockIdx.x * SCAN_B + threadIdx.x;
    if (i < NN) {
        int off = (blockIdx.x > 0) ? g_bscan[blockIdx.x - 1] : 0;
        g_rowptr[i] = g_incl[i] - g_cnt[i] + off;
    }
    if (i == 0) g_rowptr[NN] = EE;
}

__global__ void k_scatter() {
    int e = blockIdx.x * blockDim.x + threadIdx.x;
    if (e >= EE) return;
    int s = g_src[e], d = g_dst[e];
    int pos = g_rowptr[d] + atomicAdd(&g_cur[d], 1);
    g_ecol[pos] = s;
    g_ew[pos] = -g_dinv[s] * g_dinv[d];
}

// ---------------- embed: x@W + b -> LayerNorm -> ReLU  (pipelined tf32 mma) ----------------
__global__ void __launch_bounds__(256) k_embed_mma(
    const float* __restrict__ x, const float* __restrict__ W,
    const float* __restrict__ b_in, const float* __restrict__ lng,
    const float* __restrict__ lnb)
{
    extern __shared__ uint32_t smem[];
    uint32_t sbase = smem_u32(smem);
    float* stage = (float*)(smem + OFF_STAGE);
    float* biasS = (float*)(smem + OFF_EXTRA);
    float* lngS  = biasS + 128;
    float* lnbS  = lngS + 128;
    float* muS   = lnbS + 128;
    float* rsS   = muS + 128;

    int tid = threadIdx.x;
    int lane = tid & 31, warp = tid >> 5;
    int g = lane >> 2, t = lane & 3;
    int m0 = (warp >> 1) * 32, n0 = (warp & 1) * 64;
    int row0 = blockIdx.x * 128;

    if (tid < 128) {
        biasS[tid] = b_in[tid];
        lngS[tid]  = lng[tid];
        lnbS[tid]  = lnb[tid];
    }

    float acc[2][8][4];
    #pragma unroll
    for (int i = 0; i < 2; i++)
        #pragma unroll
        for (int j = 0; j < 8; j++)
            { acc[i][j][0]=0.f; acc[i][j][1]=0.f; acc[i][j][2]=0.f; acc[i][j][3]=0.f; }

    const int NCH = 4;
    load_A_async(sbase, OFF_AS0, x, row0, 0);
    load_B_async(sbase, OFF_BS0, W, 0);
    CP_COMMIT();

    for (int i = 0; i < NCH; i++) {
        int abuf = (i & 1) ? OFF_AS1 : OFF_AS0;
        int bbuf = (i & 1) ? OFF_BS1 : OFF_BS0;
        if (i + 1 < NCH) {
            int a2 = ((i + 1) & 1) ? OFF_AS1 : OFF_AS0;
            int b2 = ((i + 1) & 1) ? OFF_BS1 : OFF_BS0;
            load_A_async(sbase, a2, x, row0, i + 1);
            load_B_async(sbase, b2, W, i + 1);
            CP_COMMIT();
            CP_WAIT1();
        } else {
            CP_WAIT0();
        }
        __syncthreads();
        mma_chunk(smem + abuf, smem + bbuf, acc, m0, n0, g, t);
        __syncthreads();
    }

    acc_to_stage(stage, biasS, acc, m0, n0, g, t);
    __syncthreads();

    if (tid < 128) {
        float s = 0.f, sq = 0.f;
        #pragma unroll 8
        for (int c = 0; c < HH; c++) {
            float v = stage[tid * ST_PITCH + c];
            s += v; sq = fmaf(v, v, sq);
        }
        float mu  = s * (1.f / HH);
        float var = sq * (1.f / HH) - mu * mu;
        muS[tid] = mu;
        rsS[tid] = rsqrtf(var + EPSF);
    }
    __syncthreads();

    for (int idx = tid; idx < 128 * HH; idx += 256) {
        int r = idx >> 7, c = idx & 127;
        if (row0 + r < NN) {
            float v = stage[r * ST_PITCH + c];
            v = (v - muS[r]) * rsS[r] * lngS[c] + lnbS[c];
            g_h[(size_t)(row0 + r) * HH + c] = __float2half(fmaxf(v, 0.f));
        }
    }
}

// ---------------- cheb: g_o = h@W0 + t1@W1 + t2@W2 + b; fused BN stats ----------------
__global__ void __launch_bounds__(256) k_cheb_mma(
    const float* __restrict__ W, const float* __restrict__ bias)
{
    extern __shared__ uint32_t smem[];
    uint32_t sbase = smem_u32(smem);
    float* stage = (float*)(smem + OFF_STAGE);
    float* biasS = (float*)(smem + OFF_EXTRA);
    float* sCs   = biasS + 128;
    float* sCq   = sCs + 128;

    int tid = threadIdx.x;
    int lane = tid & 31, warp = tid >> 5;
    int g = lane >> 2, t = lane & 3;
    int m0 = (warp >> 1) * 32, n0 = (warp & 1) * 64;
    int row0 = blockIdx.x * 128;

    if (tid < 128) { biasS[tid] = bias[tid]; sCs[tid] = 0.f; sCq[tid] = 0.f; }

    float acc[2][8][4];
    #pragma unroll
    for (int i = 0; i < 2; i++)
        #pragma unroll
        for (int j = 0; j < 8; j++)
            { acc[i][j][0]=0.f; acc[i][j][1]=0.f; acc[i][j][2]=0.f; acc[i][j][3]=0.f; }

    const __half* Asrc[3] = { g_h, g_t1, g_t2 };
    const int NCH = 12;
    uint4 aregs[2], anext[2];
    ldg_A16(aregs, Asrc[0], row0, 0);
    load_B_async(sbase, OFF_BS0, W, 0);
    CP_COMMIT();

    for (int i = 0; i < NCH; i++) {
        int abuf = (i & 1) ? OFF_AS1 : OFF_AS0;
        int bbuf = (i & 1) ? OFF_BS1 : OFF_BS0;
        sts_A16(smem + abuf, aregs);
        if (i + 1 < NCH) {
            int j = i + 1;
            ldg_A16(anext, Asrc[j >> 2], row0, j & 3);
            load_B_async(sbase, (j & 1) ? OFF_BS1 : OFF_BS0,
                         W + (size_t)(j >> 2) * HH * HH, j & 3);
            CP_COMMIT();
            CP_WAIT1();
        } else {
            CP_WAIT0();
        }
        __syncthreads();
        mma_chunk(smem + abuf, smem + bbuf, acc, m0, n0, g, t);
        __syncthreads();
        aregs[0] = anext[0];
        aregs[1] = anext[1];
    }

    acc_to_stage(stage, biasS, acc, m0, n0, g, t);
    __syncthreads();

    // store fp16 + per-column BN partials (thread owns column c = tid & 127)
    {
        float ps = 0.f, pq = 0.f;
        int c = tid & 127;
        int rbase = tid >> 7;
        #pragma unroll 4
        for (int k = 0; k < 64; k++) {
            int r = rbase + k * 2;
            int row = row0 + r;
            if (row < NN) {
                float v = stage[r * ST_PITCH + c];
                g_o[(size_t)row * HH + c] = __float2half(v);
                ps += v; pq = fmaf(v, v, pq);
            }
        }
        atomicAdd(&sCs[c], ps);
        atomicAdd(&sCq[c], pq);
    }
    __syncthreads();
    if (tid < 128) {
        atomicAdd(&g_bnsum[tid], sCs[tid]);
        atomicAdd(&g_bnsq[tid],  sCq[tid]);
    }
}

// ---------------- CSR spmm #1: t1 = L_hat h; fused Dirichlet reg (fp16, x4) ----------------
__global__ void __launch_bounds__(256) k_spmm1() {
    __shared__ float blk_ss[8];
    int warp = blockIdx.x * 8 + (threadIdx.x >> 5);
    int lane = threadIdx.x & 31;
    const uint2* H = (const uint2*)g_h;
    float ss = 0.f;
    if (warp < NN) {
        int beg = g_rowptr[warp], end = g_rowptr[warp + 1];
        float4 hd = h2f4(H[(size_t)warp * 32 + lane]);
        float4 acc = make_float4(0.f, 0.f, 0.f, 0.f);
        int e = beg;
        for (; e + 4 <= end; e += 4) {
            int s0 = g_ecol[e],   s1 = g_ecol[e+1];
            int s2 = g_ecol[e+2], s3 = g_ecol[e+3];
            float w0 = g_ew[e],   w1 = g_ew[e+1];
            float w2 = g_ew[e+2], w3 = g_ew[e+3];
            float4 h0 = h2f4(H[(size_t)s0 * 32 + lane]);
            float4 h1 = h2f4(H[(size_t)s1 * 32 + lane]);
            float4 h2 = h2f4(H[(size_t)s2 * 32 + lane]);
            float4 h3 = h2f4(H[(size_t)s3 * 32 + lane]);
            acc.x = fmaf(w0,h0.x,acc.x); acc.y = fmaf(w0,h0.y,acc.y);
            acc.z = fmaf(w0,h0.z,acc.z); acc.w = fmaf(w0,h0.w,acc.w);
            float dx, dy, dz, dw;
            dx=h0.x-hd.x; dy=h0.y-hd.y; dz=h0.z-hd.z; dw=h0.w-hd.w;
            ss=fmaf(dx,dx,ss); ss=fmaf(dy,dy,ss); ss=fmaf(dz,dz,ss); ss=fmaf(dw,dw,ss);
            acc.x = fmaf(w1,h1.x,acc.x); acc.y = fmaf(w1,h1.y,acc.y);
            acc.z = fmaf(w1,h1.z,acc.z); acc.w = fmaf(w1,h1.w,acc.w);
            dx=h1.x-hd.x; dy=h1.y-hd.y; dz=h1.z-hd.z; dw=h1.w-hd.w;
            ss=fmaf(dx,dx,ss); ss=fmaf(dy,dy,ss); ss=fmaf(dz,dz,ss); ss=fmaf(dw,dw,ss);
            acc.x = fmaf(w2,h2.x,acc.x); acc.y = fmaf(w2,h2.y,acc.y);
            acc.z = fmaf(w2,h2.z,acc.z); acc.w = fmaf(w2,h2.w,acc.w);
            dx=h2.x-hd.x; dy=h2.y-hd.y; dz=h2.z-hd.z; dw=h2.w-hd.w;
            ss=fmaf(dx,dx,ss); ss=fmaf(dy,dy,ss); ss=fmaf(dz,dz,ss); ss=fmaf(dw,dw,ss);
            acc.x = fmaf(w3,h3.x,acc.x); acc.y = fmaf(w3,h3.y,acc.y);
            acc.z = fmaf(w3,h3.z,acc.z); acc.w = fmaf(w3,h3.w,acc.w);
            dx=h3.x-hd.x; dy=h3.y-hd.y; dz=h3.z-hd.z; dw=h3.w-hd.w;
            ss=fmaf(dx,dx,ss); ss=fmaf(dy,dy,ss); ss=fmaf(dz,dz,ss); ss=fmaf(dw,dw,ss);
        }
        for (; e < end; e++) {
            int s = g_ecol[e];
            float w = g_ew[e];
            float4 hv = h2f4(H[(size_t)s * 32 + lane]);
            acc.x = fmaf(w,hv.x,acc.x); acc.y = fmaf(w,hv.y,acc.y);
            acc.z = fmaf(w,hv.z,acc.z); acc.w = fmaf(w,hv.w,acc.w);
            float dx=hv.x-hd.x, dy=hv.y-hd.y, dz=hv.z-hd.z, dw=hv.w-hd.w;
            ss=fmaf(dx,dx,ss); ss=fmaf(dy,dy,ss); ss=fmaf(dz,dz,ss); ss=fmaf(dw,dw,ss);
        }
        ((uint2*)g_t1)[(size_t)warp * 32 + lane] = f2h4(acc);
    }
    #pragma unroll
    for (int off = 16; off > 0; off >>= 1)
        ss += __shfl_xor_sync(0xffffffffu, ss, off);
    if (lane == 0) blk_ss[threadIdx.x >> 5] = ss;
    __syncthreads();
    if (threadIdx.x == 0) {
        double tot = 0.0;
        #pragma unroll
        for (int j = 0; j < 8; j++) tot += (double)blk_ss[j];
        atomicAdd(&g_reg, tot);
    }
}

// ---------------- CSR spmm #2: t2 = 2 L_hat t1 - h  (fp16, x4) ----------------
__global__ void __launch_bounds__(256) k_spmm2() {
    int warp = blockIdx.x * 8 + (threadIdx.x >> 5);
    if (warp >= NN) return;
    int lane = threadIdx.x & 31;
    const uint2* T1 = (const uint2*)g_t1;
    int beg = g_rowptr[warp], end = g_rowptr[warp + 1];
    float4 acc = make_float4(0.f, 0.f, 0.f, 0.f);
    int e = beg;
    for (; e + 4 <= end; e += 4) {
        int s0 = g_ecol[e],   s1 = g_ecol[e+1];
        int s2 = g_ecol[e+2], s3 = g_ecol[e+3];
        float w0 = g_ew[e],   w1 = g_ew[e+1];
        float w2 = g_ew[e+2], w3 = g_ew[e+3];
        float4 h0 = h2f4(T1[(size_t)s0 * 32 + lane]);
        float4 h1 = h2f4(T1[(size_t)s1 * 32 + lane]);
        float4 h2 = h2f4(T1[(size_t)s2 * 32 + lane]);
        float4 h3 = h2f4(T1[(size_t)s3 * 32 + lane]);
        acc.x = fmaf(w0,h0.x,acc.x); acc.y = fmaf(w0,h0.y,acc.y);
        acc.z = fmaf(w0,h0.z,acc.z); acc.w = fmaf(w0,h0.w,acc.w);
        acc.x = fmaf(w1,h1.x,acc.x); acc.y = fmaf(w1,h1.y,acc.y);
        acc.z = fmaf(w1,h1.z,acc.z); acc.w = fmaf(w1,h1.w,acc.w);
        acc.x = fmaf(w2,h2.x,acc.x); acc.y = fmaf(w2,h2.y,acc.y);
        acc.z = fmaf(w2,h2.z,acc.z); acc.w = fmaf(w2,h2.w,acc.w);
        acc.x = fmaf(w3,h3.x,acc.x); acc.y = fmaf(w3,h3.y,acc.y);
        acc.z = fmaf(w3,h3.z,acc.z); acc.w = fmaf(w3,h3.w,acc.w);
    }
    for (; e < end; e++) {
        int s = g_ecol[e];
        float w = g_ew[e];
        float4 hv = h2f4(T1[(size_t)s * 32 + lane]);
        acc.x = fmaf(w,hv.x,acc.x); acc.y = fmaf(w,hv.y,acc.y);
        acc.z = fmaf(w,hv.z,acc.z); acc.w = fmaf(w,hv.w,acc.w);
    }
    float4 hd = h2f4(((const uint2*)g_h)[(size_t)warp * 32 + lane]);
    float4 o;
    o.x = 2.f * acc.x - hd.x;
    o.y = 2.f * acc.y - hd.y;
    o.z = 2.f * acc.z - hd.z;
    o.w = 2.f * acc.w - hd.w;
    ((uint2*)g_t2)[(size_t)warp * 32 + lane] = f2h4(o);
}

// ---------------- fused: Dirichlet reg of final h + global mean pool ----------------
__global__ void __launch_bounds__(256) k_regpool(const int* __restrict__ batch) {
    __shared__ float blk_ss[8];
    int warp = blockIdx.x * 8 + (threadIdx.x >> 5);
    int lane = threadIdx.x & 31;
    const uint2* H = (const uint2*)g_h;
    float ss = 0.f;
    if (warp < NN) {
        int beg = g_rowptr[warp], end = g_rowptr[warp + 1];
        float4 hd = h2f4(H[(size_t)warp * 32 + lane]);
        int e = beg;
        for (; e + 4 <= end; e += 4) {
            int s0 = g_ecol[e],   s1 = g_ecol[e+1];
            int s2 = g_ecol[e+2], s3 = g_ecol[e+3];
            float4 h0 = h2f4(H[(size_t)s0 * 32 + lane]);
            float4 h1 = h2f4(H[(size_t)s1 * 32 + lane]);
            float4 h2 = h2f4(H[(size_t)s2 * 32 + lane]);
            float4 h3 = h2f4(H[(size_t)s3 * 32 + lane]);
            float dx, dy, dz, dw;
            dx=h0.x-hd.x; dy=h0.y-hd.y; dz=h0.z-hd.z; dw=h0.w-hd.w;
            ss=fmaf(dx,dx,ss); ss=fmaf(dy,dy,ss); ss=fmaf(dz,dz,ss); ss=fmaf(dw,dw,ss);
            dx=h1.x-hd.x; dy=h1.y-hd.y; dz=h1.z-hd.z; dw=h1.w-hd.w;
            ss=fmaf(dx,dx,ss); ss=fmaf(dy,dy,ss); ss=fmaf(dz,dz,ss); ss=fmaf(dw,dw,ss);
            dx=h2.x-hd.x; dy=h2.y-hd.y; dz=h2.z-hd.z; dw=h2.w-hd.w;
            ss=fmaf(dx,dx,ss); ss=fmaf(dy,dy,ss); ss=fmaf(dz,dz,ss); ss=fmaf(dw,dw,ss);
            dx=h3.x-hd.x; dy=h3.y-hd.y; dz=h3.z-hd.z; dw=h3.w-hd.w;
            ss=fmaf(dx,dx,ss); ss=fmaf(dy,dy,ss); ss=fmaf(dz,dz,ss); ss=fmaf(dw,dw,ss);
        }
        for (; e < end; e++) {
            int s = g_ecol[e];
            float4 hv = h2f4(H[(size_t)s * 32 + lane]);
            float dx=hv.x-hd.x, dy=hv.y-hd.y, dz=hv.z-hd.z, dw=hv.w-hd.w;
            ss=fmaf(dx,dx,ss); ss=fmaf(dy,dy,ss); ss=fmaf(dz,dz,ss); ss=fmaf(dw,dw,ss);
        }
        // pool
        int b = batch[warp];
        float* gp = &g_gsum[(size_t)b * HH + lane * 4];
        atomicAdd(gp + 0, hd.x);
        atomicAdd(gp + 1, hd.y);
        atomicAdd(gp + 2, hd.z);
        atomicAdd(gp + 3, hd.w);
        if (lane == 0) atomicAdd(&g_gcnt[b], 1.f);
    }
    #pragma unroll
    for (int off = 16; off > 0; off >>= 1)
        ss += __shfl_xor_sync(0xffffffffu, ss, off);
    if (lane == 0) blk_ss[threadIdx.x >> 5] = ss;
    __syncthreads();
    if (threadIdx.x == 0) {
        double tot = 0.0;
        #pragma unroll
        for (int j = 0; j < 8; j++) tot += (double)blk_ss[j];
        atomicAdd(&g_reg, tot);
    }
}

// ---------------- BN finalize + apply ----------------
__global__ void k_bnfin(const float* __restrict__ bng, const float* __restrict__ bnb) {
    int c = threadIdx.x;
    float m = g_bnsum[c] * (1.f / NN);
    float v = g_bnsq[c] * (1.f / NN) - m * m;
    float sc = bng[c] * rsqrtf(v + EPSF);
    g_bnscale[c] = sc;
    g_bnshift[c] = bnb[c] - m * sc;
    g_bnsum[c] = 0.f;
    g_bnsq[c]  = 0.f;
}

__global__ void k_bnapply() {
    int i = blockIdx.x * blockDim.x + threadIdx.x;   // uint2 index over NN*32
    int c4 = i & 31;
    float4 v  = h2f4(((const uint2*)g_o)[i]);
    float4 sc = ((const float4*)g_bnscale)[c4];
    float4 sh = ((const float4*)g_bnshift)[c4];
    float4 o;
    o.x = fmaxf(fmaf(v.x, sc.x, sh.x), 0.f);
    o.y = fmaxf(fmaf(v.y, sc.y, sh.y), 0.f);
    o.z = fmaxf(fmaf(v.z, sc.z, sh.z), 0.f);
    o.w = fmaxf(fmaf(v.w, sc.w, sh.w), 0.f);
    ((uint2*)g_h)[i] = f2h4(o);
}

// ---------------- MLP head + output ----------------
__global__ void k_head(const float* __restrict__ w1, const float* __restrict__ b1,
                       const float* __restrict__ w2, const float* __restrict__ b2,
                       float* __restrict__ out, int out_size)
{
    __shared__ float gm[HH];
    __shared__ float zz[64];
    int g = blockIdx.x, t = threadIdx.x;
    float cnt = fmaxf(g_gcnt[g], 1.f);
    gm[t] = g_gsum[(size_t)g * HH + t] / cnt;
    __syncthreads();
    if (t < 64) {
        float a = b1[t];
        #pragma unroll 4
        for (int c = 0; c < HH; c++) a = fmaf(gm[c], w1[c * 64 + t], a);
        zz[t] = fmaxf(a, 0.f);
    }
    __syncthreads();
    if (t < 2) {
        float a = b2[t];
        #pragma unroll 4
        for (int k = 0; k < 64; k++) a = fmaf(zz[k], w2[k * 2 + t], a);
        out[g * 2 + t] = a;
    }
    if (g == 0 && t == 0 && out_size > 256)
        out[256] = (float)(g_reg / (4.0 * (double)EE));
}

// ---------------- launch ----------------
extern "C" void kernel_launch(void* const* d_in, const int* in_sizes, int n_in,
                              void* d_out, int out_size)
{
    const float* x      = (const float*)d_in[0];
    const float* w_in   = (const float*)d_in[1];
    const float* b_in   = (const float*)d_in[2];
    const float* ln_g   = (const float*)d_in[3];
    const float* ln_b   = (const float*)d_in[4];
    const float* cheb_w = (const float*)d_in[5];
    const float* cheb_b = (const float*)d_in[6];
    const float* bn_g   = (const float*)d_in[7];
    const float* bn_b   = (const float*)d_in[8];
    const float* w1     = (const float*)d_in[9];
    const float* b1     = (const float*)d_in[10];
    const float* w2     = (const float*)d_in[11];
    const float* b2     = (const float*)d_in[12];
    const int* ei       = (const int*)d_in[13];
    const int* batch    = (const int*)d_in[14];
    float* out = (float*)d_out;

    cudaFuncSetAttribute(k_embed_mma, cudaFuncAttributeMaxDynamicSharedMemorySize, SMEM_DYN);
    cudaFuncSetAttribute(k_cheb_mma,  cudaFuncAttributeMaxDynamicSharedMemorySize, SMEM_DYN);

    const int FB = NN * 32 / 256;            // 6250 (uint2 elements / 256)
    const int NODE_WARP_BLKS = (NN + 7) / 8; // 6250

    k_init<<<(NN + 255) / 256, 256>>>();
    k_edge_prep<<<EE / 256, 256>>>(ei);
    k_dinv<<<(NN + 255) / 256, 256>>>();
    k_scan1<<<NBLK, SCAN_B>>>();
    k_scan2<<<1, SCAN_B>>>();
    k_scan3<<<NBLK, SCAN_B>>>();
    k_scatter<<<EE / 256, 256>>>();

    k_embed_mma<<<NTILE, 256, SMEM_DYN>>>(x, w_in, b_in, ln_g, ln_b);

    for (int l = 0; l < LL; l++) {
        k_spmm1<<<NODE_WARP_BLKS, 256>>>();
        k_spmm2<<<NODE_WARP_BLKS, 256>>>();
        k_cheb_mma<<<NTILE, 256, SMEM_DYN>>>(cheb_w + (size_t)l * KK * HH * HH,
                                             cheb_b + (size_t)l * HH);
        k_bnfin<<<1, HH>>>(bn_g + (size_t)l * HH, bn_b + (size_t)l * HH);
        k_bnapply<<<FB, 256>>>();
    }

    k_regpool<<<NODE_WARP_BLKS, 256>>>(batch);
    k_head<<<GG, HH>>>(w1, b1, w2, b2, out, out_size);
}

// round 16
// speedup vs baseline: 1.2315x; 1.0045x over previous
#include <cuda_runtime.h>
#include <cuda_fp16.h>
#include <cstdint>

#define NN 50000
#define EE 800000
#define GG 128
#define HH 128
#define LL 3
#define KK 3
#define EPSF 1e-5f
#define SCAN_B 256
#define NBLK ((NN + SCAN_B - 1) / SCAN_B)   // 196
#define NTILE ((NN + 127) / 128)            // 391

// ---------------- scratch (static device globals; no allocation) ----------------
__device__ __half g_h [NN*HH];
__device__ __half g_t1[NN*HH];
__device__ __half g_t2[NN*HH];
__device__ __half g_o [NN*HH];
__device__ int   g_ecol[EE];
__device__ float g_ew [EE];
__device__ int   g_degi[NN];
__device__ float g_dinv[NN];
__device__ int   g_cnt[NN];
__device__ int   g_incl[NN];
__device__ int   g_bsum[SCAN_B];
__device__ int   g_bscan[SCAN_B];
__device__ int   g_rowptr[NN+1];
__device__ int   g_cur[NN];
__device__ float g_bnsum[HH];
__device__ float g_bnsq [HH];
__device__ float g_bnscale[HH];
__device__ float g_bnshift[HH];
__device__ double g_reg;
__device__ float g_gsum[GG*HH];
__device__ float g_gcnt[GG];

// ================= helpers =================
__device__ __forceinline__ uint32_t smem_u32(const void* p) {
    uint32_t a;
    asm("{ .reg .u64 t; cvta.to.shared.u64 t, %1; cvt.u32.u64 %0, t; }"
        : "=r"(a) : "l"(p));
    return a;
}

__device__ __forceinline__ float4 h2f4(uint2 u) {
    __half2 a = *(__half2*)&u.x, b = *(__half2*)&u.y;
    float2 fa = __half22float2(a), fb = __half22float2(b);
    return make_float4(fa.x, fa.y, fb.x, fb.y);
}
__device__ __forceinline__ uint2 f2h4(float4 v) {
    __half2 a = __floats2half2_rn(v.x, v.y);
    __half2 b = __floats2half2_rn(v.z, v.w);
    uint2 u;
    u.x = *(uint32_t*)&a;
    u.y = *(uint32_t*)&b;
    return u;
}

// D += A(16x8,row) * B(8x8,col)  tf32 inputs (raw fp32 bits), f32 accum
__device__ __forceinline__ void mma_tf32(float* d, const uint32_t* a, const uint32_t* b) {
    asm volatile(
        "mma.sync.aligned.m16n8k8.row.col.f32.tf32.tf32.f32 "
        "{%0,%1,%2,%3}, {%4,%5,%6,%7}, {%8,%9}, {%0,%1,%2,%3};"
        : "+f"(d[0]), "+f"(d[1]), "+f"(d[2]), "+f"(d[3])
        : "r"(a[0]), "r"(a[1]), "r"(a[2]), "r"(a[3]), "r"(b[0]), "r"(b[1]));
}

__device__ __forceinline__ void cp16(uint32_t dst, const void* src, bool pred) {
    int sz = pred ? 16 : 0;
    asm volatile("cp.async.cg.shared.global [%0], [%1], 16, %2;"
                 :: "r"(dst), "l"(src), "r"(sz));
}
#define CP_COMMIT() asm volatile("cp.async.commit_group;" ::: "memory")
#define CP_WAIT1()  asm volatile("cp.async.wait_group 1;" ::: "memory")
#define CP_WAIT0()  asm volatile("cp.async.wait_group 0;" ::: "memory")

// smem layout (uint32 units): double-buffered As/Bs; stage overlaps them
#define AS_PITCH 36
#define BS_PITCH 132
#define ST_PITCH 129
#define OFF_AS0  0
#define OFF_AS1  4608
#define OFF_BS0  9216
#define OFF_BS1  13440
#define OFF_STAGE 0
#define OFF_EXTRA 17664
#define SMEM_U32 (OFF_EXTRA + 128*6)
#define SMEM_DYN (SMEM_U32*4)

// async-load fp32 A chunk [128 x 32] into As buf (embed only; x is fp32)
__device__ __forceinline__ void load_A_async(
    uint32_t sbase, int bufoff, const float* __restrict__ src, int row0, int kc)
{
    const float4* s4 = (const float4*)src;
    #pragma unroll
    for (int it = 0; it < 4; it++) {
        int idx = it * 256 + threadIdx.x;
        int r = idx >> 3, c4 = idx & 7;
        const float4* gp = s4 + (size_t)(row0 + r) * 32 + kc * 8 + c4;
        uint32_t dst = sbase + (bufoff + r * AS_PITCH + c4 * 4) * 4;
        cp16(dst, gp, row0 + r < NN);
    }
}

// async-load fp32 B chunk [32 k x 128 n] into Bs buf
__device__ __forceinline__ void load_B_async(
    uint32_t sbase, int bufoff, const float* __restrict__ W, int kc)
{
    const float4* s4 = (const float4*)W;
    #pragma unroll
    for (int it = 0; it < 4; it++) {
        int idx = it * 256 + threadIdx.x;
        int r = idx >> 5, c4 = idx & 31;
        const float4* gp = s4 + (size_t)(kc * 32 + r) * 32 + c4;
        uint32_t dst = sbase + (bufoff + r * BS_PITCH + c4 * 4) * 4;
        cp16(dst, gp, true);
    }
}

// fp16 A chunk: LDG into regs (2 x uint4 = 16 halves per thread)
__device__ __forceinline__ void ldg_A16(
    uint4* r, const __half* __restrict__ src, int row0, int kc)
{
    #pragma unroll
    for (int it = 0; it < 2; it++) {
        int idx = it * 256 + threadIdx.x;
        int rr = idx >> 2, c8 = idx & 3;
        if (row0 + rr < NN)
            r[it] = ((const uint4*)src)[(size_t)(row0 + rr) * 16 + kc * 4 + c8];
        else
            r[it] = make_uint4(0u, 0u, 0u, 0u);
    }
}

// convert regs -> fp32 bits into As buf
__device__ __forceinline__ void sts_A16(uint32_t* As, const uint4* r)
{
    #pragma unroll
    for (int it = 0; it < 2; it++) {
        int idx = it * 256 + threadIdx.x;
        int rr = idx >> 2, c8 = idx & 3;
        uint32_t* p = As + rr * AS_PITCH + c8 * 8;
        const uint32_t* w = (const uint32_t*)&r[it];
        #pragma unroll
        for (int j = 0; j < 4; j++) {
            __half2 h = *(__half2*)&w[j];
            float2 f = __half22float2(h);
            p[j * 2 + 0] = __float_as_uint(f.x);
            p[j * 2 + 1] = __float_as_uint(f.y);
        }
    }
}

// one 32-wide K chunk of MMAs
__device__ __forceinline__ void mma_chunk(
    const uint32_t* As, const uint32_t* Bs,
    float acc[2][8][4], int m0, int n0, int g, int t)
{
    #pragma unroll
    for (int ks = 0; ks < 4; ks++) {
        int k0 = ks * 8;
        uint32_t a[2][4];
        #pragma unroll
        for (int mf = 0; mf < 2; mf++) {
            int r = m0 + mf * 16 + g;
            a[mf][0] = As[r * AS_PITCH + k0 + t];
            a[mf][1] = As[(r + 8) * AS_PITCH + k0 + t];
            a[mf][2] = As[r * AS_PITCH + k0 + t + 4];
            a[mf][3] = As[(r + 8) * AS_PITCH + k0 + t + 4];
        }
        #pragma unroll
        for (int nf = 0; nf < 8; nf++) {
            int c = n0 + nf * 8 + g;
            uint32_t b[2];
            b[0] = Bs[(k0 + t) * BS_PITCH + c];
            b[1] = Bs[(k0 + t + 4) * BS_PITCH + c];
            mma_tf32(acc[0][nf], a[0], b);
            mma_tf32(acc[1][nf], a[1], b);
        }
    }
}

__device__ __forceinline__ void acc_to_stage(
    float* stage, const float* biasS, float acc[2][8][4],
    int m0, int n0, int g, int t)
{
    #pragma unroll
    for (int mf = 0; mf < 2; mf++) {
        #pragma unroll
        for (int nf = 0; nf < 8; nf++) {
            int c = n0 + nf * 8 + 2 * t;
            int r = m0 + mf * 16 + g;
            stage[r * ST_PITCH + c]           = acc[mf][nf][0] + biasS[c];
            stage[r * ST_PITCH + c + 1]       = acc[mf][nf][1] + biasS[c + 1];
            stage[(r + 8) * ST_PITCH + c]     = acc[mf][nf][2] + biasS[c];
            stage[(r + 8) * ST_PITCH + c + 1] = acc[mf][nf][3] + biasS[c + 1];
        }
    }
}

// ---------------- init ----------------
__global__ void k_init() {
    int i = blockIdx.x * blockDim.x + threadIdx.x;
    if (i < NN)    { g_degi[i] = 0; g_cnt[i] = 0; g_cur[i] = 0; }
    if (i < GG*HH)   g_gsum[i] = 0.f;
    if (i < GG)      g_gcnt[i] = 0.f;
    if (i < HH)    { g_bnsum[i] = 0.f; g_bnsq[i] = 0.f; }
    if (i == 0)      g_reg = 0.0;
}

// ---------------- edge prep: degree counts only (no src/dst staging) ----------------
__global__ void k_edge_prep(const int* __restrict__ ei) {
    int e = blockIdx.x * blockDim.x + threadIdx.x;
    if (e >= EE) return;
    atomicAdd(&g_degi[ei[e]], 1);
    atomicAdd(&g_cnt[ei[EE + e]], 1);
}

// ---------------- scan (scan1 also computes dinv) ----------------
__global__ void k_scan1() {
    __shared__ int sm[SCAN_B];
    int i = blockIdx.x * SCAN_B + threadIdx.x;
    if (i < NN) {
        int d = g_degi[i];
        g_dinv[i] = d > 0 ? rsqrtf((float)d) : 0.f;
    }
    int v = (i < NN) ? g_cnt[i] : 0;
    sm[threadIdx.x] = v;
    __syncthreads();
    #pragma unroll
    for (int off = 1; off < SCAN_B; off <<= 1) {
        int t = (threadIdx.x >= off) ? sm[threadIdx.x - off] : 0;
        __syncthreads();
        sm[threadIdx.x] += t;
        __syncthreads();
    }
    if (i < NN) g_incl[i] = sm[threadIdx.x];
    if (threadIdx.x == SCAN_B - 1) g_bsum[blockIdx.x] = sm[threadIdx.x];
}

__global__ void k_scan2() {
    __shared__ int sm[SCAN_B];
    int t0 = threadIdx.x;
    sm[t0] = (t0 < NBLK) ? g_bsum[t0] : 0;
    __syncthreads();
    #pragma unroll
    for (int off = 1; off < SCAN_B; off <<= 1) {
        int t = (t0 >= off) ? sm[t0 - off] : 0;
        __syncthreads();
        sm[t0] += t;
        __syncthreads();
    }
    g_bscan[t0] = sm[t0];
}

__global__ void k_scan3() {
    int i = blockIdx.x * SCAN_B + threadIdx.x;
    if (i < NN) {
        int off = (blockIdx.x > 0) ? g_bscan[blockIdx.x - 1] : 0;
        g_rowptr[i] = g_incl[i] - g_cnt[i] + off;
    }
    if (i == 0) g_rowptr[NN] = EE;
}

// scatter reads edge_index directly
__global__ void k_scatter(const int* __restrict__ ei) {
    int e = blockIdx.x * blockDim.x + threadIdx.x;
    if (e >= EE) return;
    int s = ei[e], d = ei[EE + e];
    int pos = g_rowptr[d] + atomicAdd(&g_cur[d], 1);
    g_ecol[pos] = s;
    g_ew[pos] = -g_dinv[s] * g_dinv[d];
}

// ---------------- embed: x@W + b -> LayerNorm -> ReLU  (pipelined tf32 mma) ----------------
__global__ void __launch_bounds__(256) k_embed_mma(
    const float* __restrict__ x, const float* __restrict__ W,
    const float* __restrict__ b_in, const float* __restrict__ lng,
    const float* __restrict__ lnb)
{
    extern __shared__ uint32_t smem[];
    uint32_t sbase = smem_u32(smem);
    float* stage = (float*)(smem + OFF_STAGE);
    float* biasS = (float*)(smem + OFF_EXTRA);
    float* lngS  = biasS + 128;
    float* lnbS  = lngS + 128;
    float* muS   = lnbS + 128;
    float* rsS   = muS + 128;

    int tid = threadIdx.x;
    int lane = tid & 31, warp = tid >> 5;
    int g = lane >> 2, t = lane & 3;
    int m0 = (warp >> 1) * 32, n0 = (warp & 1) * 64;
    int row0 = blockIdx.x * 128;

    if (tid < 128) {
        biasS[tid] = b_in[tid];
        lngS[tid]  = lng[tid];
        lnbS[tid]  = lnb[tid];
    }

    float acc[2][8][4];
    #pragma unroll
    for (int i = 0; i < 2; i++)
        #pragma unroll
        for (int j = 0; j < 8; j++)
            { acc[i][j][0]=0.f; acc[i][j][1]=0.f; acc[i][j][2]=0.f; acc[i][j][3]=0.f; }

    const int NCH = 4;
    load_A_async(sbase, OFF_AS0, x, row0, 0);
    load_B_async(sbase, OFF_BS0, W, 0);
    CP_COMMIT();

    for (int i = 0; i < NCH; i++) {
        int abuf = (i & 1) ? OFF_AS1 : OFF_AS0;
        int bbuf = (i & 1) ? OFF_BS1 : OFF_BS0;
        if (i + 1 < NCH) {
            int a2 = ((i + 1) & 1) ? OFF_AS1 : OFF_AS0;
            int b2 = ((i + 1) & 1) ? OFF_BS1 : OFF_BS0;
            load_A_async(sbase, a2, x, row0, i + 1);
            load_B_async(sbase, b2, W, i + 1);
            CP_COMMIT();
            CP_WAIT1();
        } else {
            CP_WAIT0();
        }
        __syncthreads();
        mma_chunk(smem + abuf, smem + bbuf, acc, m0, n0, g, t);
        __syncthreads();
    }

    acc_to_stage(stage, biasS, acc, m0, n0, g, t);
    __syncthreads();

    if (tid < 128) {
        float s = 0.f, sq = 0.f;
        #pragma unroll 8
        for (int c = 0; c < HH; c++) {
            float v = stage[tid * ST_PITCH + c];
            s += v; sq = fmaf(v, v, sq);
        }
        float mu  = s * (1.f / HH);
        float var = sq * (1.f / HH) - mu * mu;
        muS[tid] = mu;
        rsS[tid] = rsqrtf(var + EPSF);
    }
    __syncthreads();

    for (int idx = tid; idx < 128 * HH; idx += 256) {
        int r = idx >> 7, c = idx & 127;
        if (row0 + r < NN) {
            float v = stage[r * ST_PITCH + c];
            v = (v - muS[r]) * rsS[r] * lngS[c] + lnbS[c];
            g_h[(size_t)(row0 + r) * HH + c] = __float2half(fmaxf(v, 0.f));
        }
    }
}

// ---------------- cheb: g_o = h@W0 + t1@W1 + t2@W2 + b; fused BN stats ----------------
__global__ void __launch_bounds__(256) k_cheb_mma(
    const float* __restrict__ W, const float* __restrict__ bias)
{
    extern __shared__ uint32_t smem[];
    uint32_t sbase = smem_u32(smem);
    float* stage = (float*)(smem + OFF_STAGE);
    float* biasS = (float*)(smem + OFF_EXTRA);
    float* sCs   = biasS + 128;
    float* sCq   = sCs + 128;

    int tid = threadIdx.x;
    int lane = tid & 31, warp = tid >> 5;
    int g = lane >> 2, t = lane & 3;
    int m0 = (warp >> 1) * 32, n0 = (warp & 1) * 64;
    int row0 = blockIdx.x * 128;

    if (tid < 128) { biasS[tid] = bias[tid]; sCs[tid] = 0.f; sCq[tid] = 0.f; }

    float acc[2][8][4];
    #pragma unroll
    for (int i = 0; i < 2; i++)
        #pragma unroll
        for (int j = 0; j < 8; j++)
            { acc[i][j][0]=0.f; acc[i][j][1]=0.f; acc[i][j][2]=0.f; acc[i][j][3]=0.f; }

    const __half* Asrc[3] = { g_h, g_t1, g_t2 };
    const int NCH = 12;
    uint4 aregs[2], anext[2];
    ldg_A16(aregs, Asrc[0], row0, 0);
    load_B_async(sbase, OFF_BS0, W, 0);
    CP_COMMIT();

    for (int i = 0; i < NCH; i++) {
        int abuf = (i & 1) ? OFF_AS1 : OFF_AS0;
        int bbuf = (i & 1) ? OFF_BS1 : OFF_BS0;
        sts_A16(smem + abuf, aregs);
        if (i + 1 < NCH) {
            int j = i + 1;
            ldg_A16(anext, Asrc[j >> 2], row0, j & 3);
            load_B_async(sbase, (j & 1) ? OFF_BS1 : OFF_BS0,
                         W + (size_t)(j >> 2) * HH * HH, j & 3);
            CP_COMMIT();
            CP_WAIT1();
        } else {
            CP_WAIT0();
        }
        __syncthreads();
        mma_chunk(smem + abuf, smem + bbuf, acc, m0, n0, g, t);
        __syncthreads();
        aregs[0] = anext[0];
        aregs[1] = anext[1];
    }

    acc_to_stage(stage, biasS, acc, m0, n0, g, t);
    __syncthreads();

    // store fp16 + per-column BN partials (thread owns column c = tid & 127)
    {
        float ps = 0.f, pq = 0.f;
        int c = tid & 127;
        int rbase = tid >> 7;
        #pragma unroll 4
        for (int k = 0; k < 64; k++) {
            int r = rbase + k * 2;
            int row = row0 + r;
            if (row < NN) {
                float v = stage[r * ST_PITCH + c];
                g_o[(size_t)row * HH + c] = __float2half(v);
                ps += v; pq = fmaf(v, v, pq);
            }
        }
        atomicAdd(&sCs[c], ps);
        atomicAdd(&sCq[c], pq);
    }
    __syncthreads();
    if (tid < 128) {
        atomicAdd(&g_bnsum[tid], sCs[tid]);
        atomicAdd(&g_bnsq[tid],  sCq[tid]);
    }
}

// ---------------- CSR spmm #1: t1 = L_hat h; fused Dirichlet reg (fp16, x4) ----------------
__global__ void __launch_bounds__(256) k_spmm1() {
    __shared__ float blk_ss[8];
    int warp = blockIdx.x * 8 + (threadIdx.x >> 5);
    int lane = threadIdx.x & 31;
    const uint2* H = (const uint2*)g_h;
    float ss = 0.f;
    if (warp < NN) {
        int beg = g_rowptr[warp], end = g_rowptr[warp + 1];
        float4 hd = h2f4(H[(size_t)warp * 32 + lane]);
        float4 acc = make_float4(0.f, 0.f, 0.f, 0.f);
        int e = beg;
        for (; e + 4 <= end; e += 4) {
            int s0 = g_ecol[e],   s1 = g_ecol[e+1];
            int s2 = g_ecol[e+2], s3 = g_ecol[e+3];
            float w0 = g_ew[e],   w1 = g_ew[e+1];
            float w2 = g_ew[e+2], w3 = g_ew[e+3];
            float4 h0 = h2f4(H[(size_t)s0 * 32 + lane]);
            float4 h1 = h2f4(H[(size_t)s1 * 32 + lane]);
            float4 h2 = h2f4(H[(size_t)s2 * 32 + lane]);
            float4 h3 = h2f4(H[(size_t)s3 * 32 + lane]);
            acc.x = fmaf(w0,h0.x,acc.x); acc.y = fmaf(w0,h0.y,acc.y);
            acc.z = fmaf(w0,h0.z,acc.z); acc.w = fmaf(w0,h0.w,acc.w);
            float dx, dy, dz, dw;
            dx=h0.x-hd.x; dy=h0.y-hd.y; dz=h0.z-hd.z; dw=h0.w-hd.w;
            ss=fmaf(dx,dx,ss); ss=fmaf(dy,dy,ss); ss=fmaf(dz,dz,ss); ss=fmaf(dw,dw,ss);
            acc.x = fmaf(w1,h1.x,acc.x); acc.y = fmaf(w1,h1.y,acc.y);
            acc.z = fmaf(w1,h1.z,acc.z); acc.w = fmaf(w1,h1.w,acc.w);
            dx=h1.x-hd.x; dy=h1.y-hd.y; dz=h1.z-hd.z; dw=h1.w-hd.w;
            ss=fmaf(dx,dx,ss); ss=fmaf(dy,dy,ss); ss=fmaf(dz,dz,ss); ss=fmaf(dw,dw,ss);
            acc.x = fmaf(w2,h2.x,acc.x); acc.y = fmaf(w2,h2.y,acc.y);
            acc.z = fmaf(w2,h2.z,acc.z); acc.w = fmaf(w2,h2.w,acc.w);
            dx=h2.x-hd.x; dy=h2.y-hd.y; dz=h2.z-hd.z; dw=h2.w-hd.w;
            ss=fmaf(dx,dx,ss); ss=fmaf(dy,dy,ss); ss=fmaf(dz,dz,ss); ss=fmaf(dw,dw,ss);
            acc.x = fmaf(w3,h3.x,acc.x); acc.y = fmaf(w3,h3.y,acc.y);
            acc.z = fmaf(w3,h3.z,acc.z); acc.w = fmaf(w3,h3.w,acc.w);
            dx=h3.x-hd.x; dy=h3.y-hd.y; dz=h3.z-hd.z; dw=h3.w-hd.w;
            ss=fmaf(dx,dx,ss); ss=fmaf(dy,dy,ss); ss=fmaf(dz,dz,ss); ss=fmaf(dw,dw,ss);
        }
        for (; e < end; e++) {
            int s = g_ecol[e];
            float w = g_ew[e];
            float4 hv = h2f4(H[(size_t)s * 32 + lane]);
            acc.x = fmaf(w,hv.x,acc.x); acc.y = fmaf(w,hv.y,acc.y);
            acc.z = fmaf(w,hv.z,acc.z); acc.w = fmaf(w,hv.w,acc.w);
            float dx=hv.x-hd.x, dy=hv.y-hd.y, dz=hv.z-hd.z, dw=hv.w-hd.w;
            ss=fmaf(dx,dx,ss); ss=fmaf(dy,dy,ss); ss=fmaf(dz,dz,ss); ss=fmaf(dw,dw,ss);
        }
        ((uint2*)g_t1)[(size_t)warp * 32 + lane] = f2h4(acc);
    }
    #pragma unroll
    for (int off = 16; off > 0; off >>= 1)
        ss += __shfl_xor_sync(0xffffffffu, ss, off);
    if (lane == 0) blk_ss[threadIdx.x >> 5] = ss;
    __syncthreads();
    if (threadIdx.x == 0) {
        double tot = 0.0;
        #pragma unroll
        for (int j = 0; j < 8; j++) tot += (double)blk_ss[j];
        atomicAdd(&g_reg, tot);
    }
}

// ---------------- CSR spmm #2: t2 = 2 L_hat t1 - h  (fp16, x4) ----------------
__global__ void __launch_bounds__(256) k_spmm2() {
    int warp = blockIdx.x * 8 + (threadIdx.x >> 5);
    if (warp >= NN) return;
    int lane = threadIdx.x & 31;
    const uint2* T1 = (const uint2*)g_t1;
    int beg = g_rowptr[warp], end = g_rowptr[warp + 1];
    float4 acc = make_float4(0.f, 0.f, 0.f, 0.f);
    int e = beg;
    for (; e + 4 <= end; e += 4) {
        int s0 = g_ecol[e],   s1 = g_ecol[e+1];
        int s2 = g_ecol[e+2], s3 = g_ecol[e+3];
        float w0 = g_ew[e],   w1 = g_ew[e+1];
        float w2 = g_ew[e+2], w3 = g_ew[e+3];
        float4 h0 = h2f4(T1[(size_t)s0 * 32 + lane]);
        float4 h1 = h2f4(T1[(size_t)s1 * 32 + lane]);
        float4 h2 = h2f4(T1[(size_t)s2 * 32 + lane]);
        float4 h3 = h2f4(T1[(size_t)s3 * 32 + lane]);
        acc.x = fmaf(w0,h0.x,acc.x); acc.y = fmaf(w0,h0.y,acc.y);
        acc.z = fmaf(w0,h0.z,acc.z); acc.w = fmaf(w0,h0.w,acc.w);
        acc.x = fmaf(w1,h1.x,acc.x); acc.y = fmaf(w1,h1.y,acc.y);
        acc.z = fmaf(w1,h1.z,acc.z); acc.w = fmaf(w1,h1.w,acc.w);
        acc.x = fmaf(w2,h2.x,acc.x); acc.y = fmaf(w2,h2.y,acc.y);
        acc.z = fmaf(w2,h2.z,acc.z); acc.w = fmaf(w2,h2.w,acc.w);
        acc.x = fmaf(w3,h3.x,acc.x); acc.y = fmaf(w3,h3.y,acc.y);
        acc.z = fmaf(w3,h3.z,acc.z); acc.w = fmaf(w3,h3.w,acc.w);
    }
    for (; e < end; e++) {
        int s = g_ecol[e];
        float w = g_ew[e];
        float4 hv = h2f4(T1[(size_t)s * 32 + lane]);
        acc.x = fmaf(w,hv.x,acc.x); acc.y = fmaf(w,hv.y,acc.y);
        acc.z = fmaf(w,hv.z,acc.z); acc.w = fmaf(w,hv.w,acc.w);
    }
    float4 hd = h2f4(((const uint2*)g_h)[(size_t)warp * 32 + lane]);
    float4 o;
    o.x = 2.f * acc.x - hd.x;
    o.y = 2.f * acc.y - hd.y;
    o.z = 2.f * acc.z - hd.z;
    o.w = 2.f * acc.w - hd.w;
    ((uint2*)g_t2)[(size_t)warp * 32 + lane] = f2h4(o);
}

// ---------------- fused: Dirichlet reg of final h + global mean pool ----------------
__global__ void __launch_bounds__(256) k_regpool(const int* __restrict__ batch) {
    __shared__ float blk_ss[8];
    int warp = blockIdx.x * 8 + (threadIdx.x >> 5);
    int lane = threadIdx.x & 31;
    const uint2* H = (const uint2*)g_h;
    float ss = 0.f;
    if (warp < NN) {
        int beg = g_rowptr[warp], end = g_rowptr[warp + 1];
        float4 hd = h2f4(H[(size_t)warp * 32 + lane]);
        int e = beg;
        for (; e + 4 <= end; e += 4) {
            int s0 = g_ecol[e],   s1 = g_ecol[e+1];
            int s2 = g_ecol[e+2], s3 = g_ecol[e+3];
            float4 h0 = h2f4(H[(size_t)s0 * 32 + lane]);
            float4 h1 = h2f4(H[(size_t)s1 * 32 + lane]);
            float4 h2 = h2f4(H[(size_t)s2 * 32 + lane]);
            float4 h3 = h2f4(H[(size_t)s3 * 32 + lane]);
            float dx, dy, dz, dw;
            dx=h0.x-hd.x; dy=h0.y-hd.y; dz=h0.z-hd.z; dw=h0.w-hd.w;
            ss=fmaf(dx,dx,ss); ss=fmaf(dy,dy,ss); ss=fmaf(dz,dz,ss); ss=fmaf(dw,dw,ss);
            dx=h1.x-hd.x; dy=h1.y-hd.y; dz=h1.z-hd.z; dw=h1.w-hd.w;
            ss=fmaf(dx,dx,ss); ss=fmaf(dy,dy,ss); ss=fmaf(dz,dz,ss); ss=fmaf(dw,dw,ss);
            dx=h2.x-hd.x; dy=h2.y-hd.y; dz=h2.z-hd.z; dw=h2.w-hd.w;
            ss=fmaf(dx,dx,ss); ss=fmaf(dy,dy,ss); ss=fmaf(dz,dz,ss); ss=fmaf(dw,dw,ss);
            dx=h3.x-hd.x; dy=h3.y-hd.y; dz=h3.z-hd.z; dw=h3.w-hd.w;
            ss=fmaf(dx,dx,ss); ss=fmaf(dy,dy,ss); ss=fmaf(dz,dz,ss); ss=fmaf(dw,dw,ss);
        }
        for (; e < end; e++) {
            int s = g_ecol[e];
            float4 hv = h2f4(H[(size_t)s * 32 + lane]);
            float dx=hv.x-hd.x, dy=hv.y-hd.y, dz=hv.z-hd.z, dw=hv.w-hd.w;
            ss=fmaf(dx,dx,ss); ss=fmaf(dy,dy,ss); ss=fmaf(dz,dz,ss); ss=fmaf(dw,dw,ss);
        }
        // pool
        int b = batch[warp];
        float* gp = &g_gsum[(size_t)b * HH + lane * 4];
        atomicAdd(gp + 0, hd.x);
        atomicAdd(gp + 1, hd.y);
        atomicAdd(gp + 2, hd.z);
        atomicAdd(gp + 3, hd.w);
        if (lane == 0) atomicAdd(&g_gcnt[b], 1.f);
    }
    #pragma unroll
    for (int off = 16; off > 0; off >>= 1)
        ss += __shfl_xor_sync(0xffffffffu, ss, off);
    if (lane == 0) blk_ss[threadIdx.x >> 5] = ss;
    __syncthreads();
    if (threadIdx.x == 0) {
        double tot = 0.0;
        #pragma unroll
        for (int j = 0; j < 8; j++) tot += (double)blk_ss[j];
        atomicAdd(&g_reg, tot);
    }
}

// ---------------- BN finalize + apply ----------------
__global__ void k_bnfin(const float* __restrict__ bng, const float* __restrict__ bnb) {
    int c = threadIdx.x;
    float m = g_bnsum[c] * (1.f / NN);
    float v = g_bnsq[c] * (1.f / NN) - m * m;
    float sc = bng[c] * rsqrtf(v + EPSF);
    g_bnscale[c] = sc;
    g_bnshift[c] = bnb[c] - m * sc;
    g_bnsum[c] = 0.f;
    g_bnsq[c]  = 0.f;
}

__global__ void k_bnapply() {
    int i = blockIdx.x * blockDim.x + threadIdx.x;   // uint2 index over NN*32
    int c4 = i & 31;
    float4 v  = h2f4(((const uint2*)g_o)[i]);
    float4 sc = ((const float4*)g_bnscale)[c4];
    float4 sh = ((const float4*)g_bnshift)[c4];
    float4 o;
    o.x = fmaxf(fmaf(v.x, sc.x, sh.x), 0.f);
    o.y = fmaxf(fmaf(v.y, sc.y, sh.y), 0.f);
    o.z = fmaxf(fmaf(v.z, sc.z, sh.z), 0.f);
    o.w = fmaxf(fmaf(v.w, sc.w, sh.w), 0.f);
    ((uint2*)g_h)[i] = f2h4(o);
}

// ---------------- MLP head + output ----------------
__global__ void k_head(const float* __restrict__ w1, const float* __restrict__ b1,
                       const float* __restrict__ w2, const float* __restrict__ b2,
                       float* __restrict__ out, int out_size)
{
    __shared__ float gm[HH];
    __shared__ float zz[64];
    int g = blockIdx.x, t = threadIdx.x;
    float cnt = fmaxf(g_gcnt[g], 1.f);
    gm[t] = g_gsum[(size_t)g * HH + t] / cnt;
    __syncthreads();
    if (t < 64) {
        float a = b1[t];
        #pragma unroll 4
        for (int c = 0; c < HH; c++) a = fmaf(gm[c], w1[c * 64 + t], a);
        zz[t] = fmaxf(a, 0.f);
    }
    __syncthreads();
    if (t < 2) {
        float a = b2[t];
        #pragma unroll 4
        for (int k = 0; k < 64; k++) a = fmaf(zz[k], w2[k * 2 + t], a);
        out[g * 2 + t] = a;
    }
    if (g == 0 && t == 0 && out_size > 256)
        out[256] = (float)(g_reg / (4.0 * (double)EE));
}

// ---------------- launch ----------------
extern "C" void kernel_launch(void* const* d_in, const int* in_sizes, int n_in,
                              void* d_out, int out_size)
{
    const float* x      = (const float*)d_in[0];
    const float* w_in   = (const float*)d_in[1];
    const float* b_in   = (const float*)d_in[2];
    const float* ln_g   = (const float*)d_in[3];
    const float* ln_b   = (const float*)d_in[4];
    const float* cheb_w = (const float*)d_in[5];
    const float* cheb_b = (const float*)d_in[6];
    const float* bn_g   = (const float*)d_in[7];
    const float* bn_b   = (const float*)d_in[8];
    const float* w1     = (const float*)d_in[9];
    const float* b1     = (const float*)d_in[10];
    const float* w2     = (const float*)d_in[11];
    const float* b2     = (const float*)d_in[12];
    const int* ei       = (const int*)d_in[13];
    const int* batch    = (const int*)d_in[14];
    float* out = (float*)d_out;

    cudaFuncSetAttribute(k_embed_mma, cudaFuncAttributeMaxDynamicSharedMemorySize, SMEM_DYN);
    cudaFuncSetAttribute(k_cheb_mma,  cudaFuncAttributeMaxDynamicSharedMemorySize, SMEM_DYN);

    const int FB = NN * 32 / 256;            // 6250 (uint2 elements / 256)
    const int NODE_WARP_BLKS = (NN + 7) / 8; // 6250

    k_init<<<(NN + 255) / 256, 256>>>();
    k_edge_prep<<<EE / 256, 256>>>(ei);
    k_scan1<<<NBLK, SCAN_B>>>();             // + dinv
    k_scan2<<<1, SCAN_B>>>();
    k_scan3<<<NBLK, SCAN_B>>>();
    k_scatter<<<EE / 256, 256>>>(ei);

    k_embed_mma<<<NTILE, 256, SMEM_DYN>>>(x, w_in, b_in, ln_g, ln_b);

    for (int l = 0; l < LL; l++) {
        k_spmm1<<<NODE_WARP_BLKS, 256>>>();
        k_spmm2<<<NODE_WARP_BLKS, 256>>>();
        k_cheb_mma<<<NTILE, 256, SMEM_DYN>>>(cheb_w + (size_t)l * KK * HH * HH,
                                             cheb_b + (size_t)l * HH);
        k_bnfin<<<1, HH>>>(bn_g + (size_t)l * HH, bn_b + (size_t)l * HH);
        k_bnapply<<<FB, 256>>>();
    }

    k_regpool<<<NODE_WARP_BLKS, 256>>>(batch);
    k_head<<<GG, HH>>>(w1, b1, w2, b2, out, out_size);
}

// round 17
// speedup vs baseline: 1.2402x; 1.0070x over previous
#include <cuda_runtime.h>
#include <cuda_fp16.h>
#include <cstdint>

#define NN 50000
#define EE 800000
#define GG 128
#define HH 128
#define LL 3
#define KK 3
#define EPSF 1e-5f
#define SCAN_B 256
#define NBLK ((NN + SCAN_B - 1) / SCAN_B)   // 196
#define NTILE ((NN + 127) / 128)            // 391

// ---------------- scratch (static device globals; no allocation) ----------------
__device__ __half g_h [NN*HH];
__device__ __half g_t1[NN*HH];
__device__ __half g_t2[NN*HH];
__device__ __half g_o [NN*HH];
__device__ int   g_ecol[EE];
__device__ float g_ew [EE];
__device__ int   g_degi[NN];
__device__ float g_dinv[NN];
__device__ int   g_cnt[NN];
__device__ int   g_incl[NN];
__device__ int   g_bsum[SCAN_B];
__device__ int   g_rowptr[NN+1];
__device__ int   g_cur[NN];
__device__ float g_bnsum[LL*HH];   // per-layer BN stats (no reset needed)
__device__ float g_bnsq [LL*HH];
__device__ double g_reg;
__device__ float g_gsum[GG*HH];
__device__ float g_gcnt[GG];

// ================= helpers =================
__device__ __forceinline__ uint32_t smem_u32(const void* p) {
    uint32_t a;
    asm("{ .reg .u64 t; cvta.to.shared.u64 t, %1; cvt.u32.u64 %0, t; }"
        : "=r"(a) : "l"(p));
    return a;
}

__device__ __forceinline__ float4 h2f4(uint2 u) {
    __half2 a = *(__half2*)&u.x, b = *(__half2*)&u.y;
    float2 fa = __half22float2(a), fb = __half22float2(b);
    return make_float4(fa.x, fa.y, fb.x, fb.y);
}
__device__ __forceinline__ uint2 f2h4(float4 v) {
    __half2 a = __floats2half2_rn(v.x, v.y);
    __half2 b = __floats2half2_rn(v.z, v.w);
    uint2 u;
    u.x = *(uint32_t*)&a;
    u.y = *(uint32_t*)&b;
    return u;
}

// D += A(16x8,row) * B(8x8,col)  tf32 inputs (raw fp32 bits), f32 accum
__device__ __forceinline__ void mma_tf32(float* d, const uint32_t* a, const uint32_t* b) {
    asm volatile(
        "mma.sync.aligned.m16n8k8.row.col.f32.tf32.tf32.f32 "
        "{%0,%1,%2,%3}, {%4,%5,%6,%7}, {%8,%9}, {%0,%1,%2,%3};"
        : "+f"(d[0]), "+f"(d[1]), "+f"(d[2]), "+f"(d[3])
        : "r"(a[0]), "r"(a[1]), "r"(a[2]), "r"(a[3]), "r"(b[0]), "r"(b[1]));
}

__device__ __forceinline__ void cp16(uint32_t dst, const void* src, bool pred) {
    int sz = pred ? 16 : 0;
    asm volatile("cp.async.cg.shared.global [%0], [%1], 16, %2;"
                 :: "r"(dst), "l"(src), "r"(sz));
}
#define CP_COMMIT() asm volatile("cp.async.commit_group;" ::: "memory")
#define CP_WAIT1()  asm volatile("cp.async.wait_group 1;" ::: "memory")
#define CP_WAIT0()  asm volatile("cp.async.wait_group 0;" ::: "memory")

// smem layout (uint32 units): double-buffered As/Bs; stage overlaps them
#define AS_PITCH 36
#define BS_PITCH 132
#define ST_PITCH 129
#define OFF_AS0  0
#define OFF_AS1  4608
#define OFF_BS0  9216
#define OFF_BS1  13440
#define OFF_STAGE 0
#define OFF_EXTRA 17664
#define SMEM_U32 (OFF_EXTRA + 128*6)
#define SMEM_DYN (SMEM_U32*4)

// async-load fp32 A chunk [128 x 32] into As buf (embed only; x is fp32)
__device__ __forceinline__ void load_A_async(
    uint32_t sbase, int bufoff, const float* __restrict__ src, int row0, int kc)
{
    const float4* s4 = (const float4*)src;
    #pragma unroll
    for (int it = 0; it < 4; it++) {
        int idx = it * 256 + threadIdx.x;
        int r = idx >> 3, c4 = idx & 7;
        const float4* gp = s4 + (size_t)(row0 + r) * 32 + kc * 8 + c4;
        uint32_t dst = sbase + (bufoff + r * AS_PITCH + c4 * 4) * 4;
        cp16(dst, gp, row0 + r < NN);
    }
}

// async-load fp32 B chunk [32 k x 128 n] into Bs buf
__device__ __forceinline__ void load_B_async(
    uint32_t sbase, int bufoff, const float* __restrict__ W, int kc)
{
    const float4* s4 = (const float4*)W;
    #pragma unroll
    for (int it = 0; it < 4; it++) {
        int idx = it * 256 + threadIdx.x;
        int r = idx >> 5, c4 = idx & 31;
        const float4* gp = s4 + (size_t)(kc * 32 + r) * 32 + c4;
        uint32_t dst = sbase + (bufoff + r * BS_PITCH + c4 * 4) * 4;
        cp16(dst, gp, true);
    }
}

// fp16 A chunk: LDG into regs (2 x uint4 = 16 halves per thread)
__device__ __forceinline__ void ldg_A16(
    uint4* r, const __half* __restrict__ src, int row0, int kc)
{
    #pragma unroll
    for (int it = 0; it < 2; it++) {
        int idx = it * 256 + threadIdx.x;
        int rr = idx >> 2, c8 = idx & 3;
        if (row0 + rr < NN)
            r[it] = ((const uint4*)src)[(size_t)(row0 + rr) * 16 + kc * 4 + c8];
        else
            r[it] = make_uint4(0u, 0u, 0u, 0u);
    }
}

// convert regs -> fp32 bits into As buf
__device__ __forceinline__ void sts_A16(uint32_t* As, const uint4* r)
{
    #pragma unroll
    for (int it = 0; it < 2; it++) {
        int idx = it * 256 + threadIdx.x;
        int rr = idx >> 2, c8 = idx & 3;
        uint32_t* p = As + rr * AS_PITCH + c8 * 8;
        const uint32_t* w = (const uint32_t*)&r[it];
        #pragma unroll
        for (int j = 0; j < 4; j++) {
            __half2 h = *(__half2*)&w[j];
            float2 f = __half22float2(h);
            p[j * 2 + 0] = __float_as_uint(f.x);
            p[j * 2 + 1] = __float_as_uint(f.y);
        }
    }
}

// one 32-wide K chunk of MMAs
__device__ __forceinline__ void mma_chunk(
    const uint32_t* As, const uint32_t* Bs,
    float acc[2][8][4], int m0, int n0, int g, int t)
{
    #pragma unroll
    for (int ks = 0; ks < 4; ks++) {
        int k0 = ks * 8;
        uint32_t a[2][4];
        #pragma unroll
        for (int mf = 0; mf < 2; mf++) {
            int r = m0 + mf * 16 + g;
            a[mf][0] = As[r * AS_PITCH + k0 + t];
            a[mf][1] = As[(r + 8) * AS_PITCH + k0 + t];
            a[mf][2] = As[r * AS_PITCH + k0 + t + 4];
            a[mf][3] = As[(r + 8) * AS_PITCH + k0 + t + 4];
        }
        #pragma unroll
        for (int nf = 0; nf < 8; nf++) {
            int c = n0 + nf * 8 + g;
            uint32_t b[2];
            b[0] = Bs[(k0 + t) * BS_PITCH + c];
            b[1] = Bs[(k0 + t + 4) * BS_PITCH + c];
            mma_tf32(acc[0][nf], a[0], b);
            mma_tf32(acc[1][nf], a[1], b);
        }
    }
}

__device__ __forceinline__ void acc_to_stage(
    float* stage, const float* biasS, float acc[2][8][4],
    int m0, int n0, int g, int t)
{
    #pragma unroll
    for (int mf = 0; mf < 2; mf++) {
        #pragma unroll
        for (int nf = 0; nf < 8; nf++) {
            int c = n0 + nf * 8 + 2 * t;
            int r = m0 + mf * 16 + g;
            stage[r * ST_PITCH + c]           = acc[mf][nf][0] + biasS[c];
            stage[r * ST_PITCH + c + 1]       = acc[mf][nf][1] + biasS[c + 1];
            stage[(r + 8) * ST_PITCH + c]     = acc[mf][nf][2] + biasS[c];
            stage[(r + 8) * ST_PITCH + c + 1] = acc[mf][nf][3] + biasS[c + 1];
        }
    }
}

// ---------------- init ----------------
__global__ void k_init() {
    int i = blockIdx.x * blockDim.x + threadIdx.x;
    if (i < NN)    { g_degi[i] = 0; g_cnt[i] = 0; g_cur[i] = 0; }
    if (i < GG*HH)   g_gsum[i] = 0.f;
    if (i < GG)      g_gcnt[i] = 0.f;
    if (i < LL*HH) { g_bnsum[i] = 0.f; g_bnsq[i] = 0.f; }
    if (i == 0)      g_reg = 0.0;
}

// ---------------- edge prep: degree counts only ----------------
__global__ void k_edge_prep(const int* __restrict__ ei) {
    int e = blockIdx.x * blockDim.x + threadIdx.x;
    if (e >= EE) return;
    atomicAdd(&g_degi[ei[e]], 1);
    atomicAdd(&g_cnt[ei[EE + e]], 1);
}

// ---------------- scan1: block-local inclusive scan + dinv ----------------
__global__ void k_scan1() {
    __shared__ int sm[SCAN_B];
    int i = blockIdx.x * SCAN_B + threadIdx.x;
    if (i < NN) {
        int d = g_degi[i];
        g_dinv[i] = d > 0 ? rsqrtf((float)d) : 0.f;
    }
    int v = (i < NN) ? g_cnt[i] : 0;
    sm[threadIdx.x] = v;
    __syncthreads();
    #pragma unroll
    for (int off = 1; off < SCAN_B; off <<= 1) {
        int t = (threadIdx.x >= off) ? sm[threadIdx.x - off] : 0;
        __syncthreads();
        sm[threadIdx.x] += t;
        __syncthreads();
    }
    if (i < NN) g_incl[i] = sm[threadIdx.x];
    if (threadIdx.x == SCAN_B - 1) g_bsum[blockIdx.x] = sm[threadIdx.x];
}

// ---------------- scan3: per-block prefix of g_bsum reduced in-block (scan2 deleted) ----------------
__global__ void k_scan3() {
    __shared__ int sm[SCAN_B];
    int t0 = threadIdx.x;
    sm[t0] = (t0 < blockIdx.x) ? g_bsum[t0] : 0;   // NBLK=196 <= 256
    __syncthreads();
    #pragma unroll
    for (int off = SCAN_B / 2; off > 0; off >>= 1) {
        if (t0 < off) sm[t0] += sm[t0 + off];
        __syncthreads();
    }
    int off0 = sm[0];
    int i = blockIdx.x * SCAN_B + t0;
    if (i < NN)
        g_rowptr[i] = g_incl[i] - g_cnt[i] + off0;
    if (i == 0) g_rowptr[NN] = EE;
}

// scatter reads edge_index directly
__global__ void k_scatter(const int* __restrict__ ei) {
    int e = blockIdx.x * blockDim.x + threadIdx.x;
    if (e >= EE) return;
    int s = ei[e], d = ei[EE + e];
    int pos = g_rowptr[d] + atomicAdd(&g_cur[d], 1);
    g_ecol[pos] = s;
    g_ew[pos] = -g_dinv[s] * g_dinv[d];
}

// ---------------- embed: x@W + b -> LayerNorm -> ReLU  (pipelined tf32 mma) ----------------
__global__ void __launch_bounds__(256) k_embed_mma(
    const float* __restrict__ x, const float* __restrict__ W,
    const float* __restrict__ b_in, const float* __restrict__ lng,
    const float* __restrict__ lnb)
{
    extern __shared__ uint32_t smem[];
    uint32_t sbase = smem_u32(smem);
    float* stage = (float*)(smem + OFF_STAGE);
    float* biasS = (float*)(smem + OFF_EXTRA);
    float* lngS  = biasS + 128;
    float* lnbS  = lngS + 128;
    float* muS   = lnbS + 128;
    float* rsS   = muS + 128;

    int tid = threadIdx.x;
    int lane = tid & 31, warp = tid >> 5;
    int g = lane >> 2, t = lane & 3;
    int m0 = (warp >> 1) * 32, n0 = (warp & 1) * 64;
    int row0 = blockIdx.x * 128;

    if (tid < 128) {
        biasS[tid] = b_in[tid];
        lngS[tid]  = lng[tid];
        lnbS[tid]  = lnb[tid];
    }

    float acc[2][8][4];
    #pragma unroll
    for (int i = 0; i < 2; i++)
        #pragma unroll
        for (int j = 0; j < 8; j++)
            { acc[i][j][0]=0.f; acc[i][j][1]=0.f; acc[i][j][2]=0.f; acc[i][j][3]=0.f; }

    const int NCH = 4;
    load_A_async(sbase, OFF_AS0, x, row0, 0);
    load_B_async(sbase, OFF_BS0, W, 0);
    CP_COMMIT();

    for (int i = 0; i < NCH; i++) {
        int abuf = (i & 1) ? OFF_AS1 : OFF_AS0;
        int bbuf = (i & 1) ? OFF_BS1 : OFF_BS0;
        if (i + 1 < NCH) {
            int a2 = ((i + 1) & 1) ? OFF_AS1 : OFF_AS0;
            int b2 = ((i + 1) & 1) ? OFF_BS1 : OFF_BS0;
            load_A_async(sbase, a2, x, row0, i + 1);
            load_B_async(sbase, b2, W, i + 1);
            CP_COMMIT();
            CP_WAIT1();
        } else {
            CP_WAIT0();
        }
        __syncthreads();
        mma_chunk(smem + abuf, smem + bbuf, acc, m0, n0, g, t);
        __syncthreads();
    }

    acc_to_stage(stage, biasS, acc, m0, n0, g, t);
    __syncthreads();

    if (tid < 128) {
        float s = 0.f, sq = 0.f;
        #pragma unroll 8
        for (int c = 0; c < HH; c++) {
            float v = stage[tid * ST_PITCH + c];
            s += v; sq = fmaf(v, v, sq);
        }
        float mu  = s * (1.f / HH);
        float var = sq * (1.f / HH) - mu * mu;
        muS[tid] = mu;
        rsS[tid] = rsqrtf(var + EPSF);
    }
    __syncthreads();

    for (int idx = tid; idx < 128 * HH; idx += 256) {
        int r = idx >> 7, c = idx & 127;
        if (row0 + r < NN) {
            float v = stage[r * ST_PITCH + c];
            v = (v - muS[r]) * rsS[r] * lngS[c] + lnbS[c];
            g_h[(size_t)(row0 + r) * HH + c] = __float2half(fmaxf(v, 0.f));
        }
    }
}

// ---------------- cheb: g_o = h@W0 + t1@W1 + t2@W2 + b; per-layer BN stats ----------------
__global__ void __launch_bounds__(256) k_cheb_mma(
    int l, const float* __restrict__ W, const float* __restrict__ bias)
{
    extern __shared__ uint32_t smem[];
    uint32_t sbase = smem_u32(smem);
    float* stage = (float*)(smem + OFF_STAGE);
    float* biasS = (float*)(smem + OFF_EXTRA);
    float* sCs   = biasS + 128;
    float* sCq   = sCs + 128;

    int tid = threadIdx.x;
    int lane = tid & 31, warp = tid >> 5;
    int g = lane >> 2, t = lane & 3;
    int m0 = (warp >> 1) * 32, n0 = (warp & 1) * 64;
    int row0 = blockIdx.x * 128;

    if (tid < 128) { biasS[tid] = bias[tid]; sCs[tid] = 0.f; sCq[tid] = 0.f; }

    float acc[2][8][4];
    #pragma unroll
    for (int i = 0; i < 2; i++)
        #pragma unroll
        for (int j = 0; j < 8; j++)
            { acc[i][j][0]=0.f; acc[i][j][1]=0.f; acc[i][j][2]=0.f; acc[i][j][3]=0.f; }

    const __half* Asrc[3] = { g_h, g_t1, g_t2 };
    const int NCH = 12;
    uint4 aregs[2], anext[2];
    ldg_A16(aregs, Asrc[0], row0, 0);
    load_B_async(sbase, OFF_BS0, W, 0);
    CP_COMMIT();

    for (int i = 0; i < NCH; i++) {
        int abuf = (i & 1) ? OFF_AS1 : OFF_AS0;
        int bbuf = (i & 1) ? OFF_BS1 : OFF_BS0;
        sts_A16(smem + abuf, aregs);
        if (i + 1 < NCH) {
            int j = i + 1;
            ldg_A16(anext, Asrc[j >> 2], row0, j & 3);
            load_B_async(sbase, (j & 1) ? OFF_BS1 : OFF_BS0,
                         W + (size_t)(j >> 2) * HH * HH, j & 3);
            CP_COMMIT();
            CP_WAIT1();
        } else {
            CP_WAIT0();
        }
        __syncthreads();
        mma_chunk(smem + abuf, smem + bbuf, acc, m0, n0, g, t);
        __syncthreads();
        aregs[0] = anext[0];
        aregs[1] = anext[1];
    }

    acc_to_stage(stage, biasS, acc, m0, n0, g, t);
    __syncthreads();

    // store fp16 + per-column BN partials (thread owns column c = tid & 127)
    {
        float ps = 0.f, pq = 0.f;
        int c = tid & 127;
        int rbase = tid >> 7;
        #pragma unroll 4
        for (int k = 0; k < 64; k++) {
            int r = rbase + k * 2;
            int row = row0 + r;
            if (row < NN) {
                float v = stage[r * ST_PITCH + c];
                g_o[(size_t)row * HH + c] = __float2half(v);
                ps += v; pq = fmaf(v, v, pq);
            }
        }
        atomicAdd(&sCs[c], ps);
        atomicAdd(&sCq[c], pq);
    }
    __syncthreads();
    if (tid < 128) {
        atomicAdd(&g_bnsum[l * HH + tid], sCs[tid]);
        atomicAdd(&g_bnsq[l * HH + tid],  sCq[tid]);
    }
}

// ---------------- CSR spmm #1: t1 = L_hat h; fused Dirichlet reg (fp16, x4) ----------------
__global__ void __launch_bounds__(256) k_spmm1() {
    __shared__ float blk_ss[8];
    int warp = blockIdx.x * 8 + (threadIdx.x >> 5);
    int lane = threadIdx.x & 31;
    const uint2* H = (const uint2*)g_h;
    float ss = 0.f;
    if (warp < NN) {
        int beg = g_rowptr[warp], end = g_rowptr[warp + 1];
        float4 hd = h2f4(H[(size_t)warp * 32 + lane]);
        float4 acc = make_float4(0.f, 0.f, 0.f, 0.f);
        int e = beg;
        for (; e + 4 <= end; e += 4) {
            int s0 = g_ecol[e],   s1 = g_ecol[e+1];
            int s2 = g_ecol[e+2], s3 = g_ecol[e+3];
            float w0 = g_ew[e],   w1 = g_ew[e+1];
            float w2 = g_ew[e+2], w3 = g_ew[e+3];
            float4 h0 = h2f4(H[(size_t)s0 * 32 + lane]);
            float4 h1 = h2f4(H[(size_t)s1 * 32 + lane]);
            float4 h2 = h2f4(H[(size_t)s2 * 32 + lane]);
            float4 h3 = h2f4(H[(size_t)s3 * 32 + lane]);
            acc.x = fmaf(w0,h0.x,acc.x); acc.y = fmaf(w0,h0.y,acc.y);
            acc.z = fmaf(w0,h0.z,acc.z); acc.w = fmaf(w0,h0.w,acc.w);
            float dx, dy, dz, dw;
            dx=h0.x-hd.x; dy=h0.y-hd.y; dz=h0.z-hd.z; dw=h0.w-hd.w;
            ss=fmaf(dx,dx,ss); ss=fmaf(dy,dy,ss); ss=fmaf(dz,dz,ss); ss=fmaf(dw,dw,ss);
            acc.x = fmaf(w1,h1.x,acc.x); acc.y = fmaf(w1,h1.y,acc.y);
            acc.z = fmaf(w1,h1.z,acc.z); acc.w = fmaf(w1,h1.w,acc.w);
            dx=h1.x-hd.x; dy=h1.y-hd.y; dz=h1.z-hd.z; dw=h1.w-hd.w;
            ss=fmaf(dx,dx,ss); ss=fmaf(dy,dy,ss); ss=fmaf(dz,dz,ss); ss=fmaf(dw,dw,ss);
            acc.x = fmaf(w2,h2.x,acc.x); acc.y = fmaf(w2,h2.y,acc.y);
            acc.z = fmaf(w2,h2.z,acc.z); acc.w = fmaf(w2,h2.w,acc.w);
            dx=h2.x-hd.x; dy=h2.y-hd.y; dz=h2.z-hd.z; dw=h2.w-hd.w;
            ss=fmaf(dx,dx,ss); ss=fmaf(dy,dy,ss); ss=fmaf(dz,dz,ss); ss=fmaf(dw,dw,ss);
            acc.x = fmaf(w3,h3.x,acc.x); acc.y = fmaf(w3,h3.y,acc.y);
            acc.z = fmaf(w3,h3.z,acc.z); acc.w = fmaf(w3,h3.w,acc.w);
            dx=h3.x-hd.x; dy=h3.y-hd.y; dz=h3.z-hd.z; dw=h3.w-hd.w;
            ss=fmaf(dx,dx,ss); ss=fmaf(dy,dy,ss); ss=fmaf(dz,dz,ss); ss=fmaf(dw,dw,ss);
        }
        for (; e < end; e++) {
            int s = g_ecol[e];
            float w = g_ew[e];
            float4 hv = h2f4(H[(size_t)s * 32 + lane]);
            acc.x = fmaf(w,hv.x,acc.x); acc.y = fmaf(w,hv.y,acc.y);
            acc.z = fmaf(w,hv.z,acc.z); acc.w = fmaf(w,hv.w,acc.w);
            float dx=hv.x-hd.x, dy=hv.y-hd.y, dz=hv.z-hd.z, dw=hv.w-hd.w;
            ss=fmaf(dx,dx,ss); ss=fmaf(dy,dy,ss); ss=fmaf(dz,dz,ss); ss=fmaf(dw,dw,ss);
        }
        ((uint2*)g_t1)[(size_t)warp * 32 + lane] = f2h4(acc);
    }
    #pragma unroll
    for (int off = 16; off > 0; off >>= 1)
        ss += __shfl_xor_sync(0xffffffffu, ss, off);
    if (lane == 0) blk_ss[threadIdx.x >> 5] = ss;
    __syncthreads();
    if (threadIdx.x == 0) {
        double tot = 0.0;
        #pragma unroll
        for (int j = 0; j < 8; j++) tot += (double)blk_ss[j];
        atomicAdd(&g_reg, tot);
    }
}

// ---------------- CSR spmm #2: t2 = 2 L_hat t1 - h  (fp16, x4) ----------------
__global__ void __launch_bounds__(256) k_spmm2() {
    int warp = blockIdx.x * 8 + (threadIdx.x >> 5);
    if (warp >= NN) return;
    int lane = threadIdx.x & 31;
    const uint2* T1 = (const uint2*)g_t1;
    int beg = g_rowptr[warp], end = g_rowptr[warp + 1];
    float4 acc = make_float4(0.f, 0.f, 0.f, 0.f);
    int e = beg;
    for (; e + 4 <= end; e += 4) {
        int s0 = g_ecol[e],   s1 = g_ecol[e+1];
        int s2 = g_ecol[e+2], s3 = g_ecol[e+3];
        float w0 = g_ew[e],   w1 = g_ew[e+1];
        float w2 = g_ew[e+2], w3 = g_ew[e+3];
        float4 h0 = h2f4(T1[(size_t)s0 * 32 + lane]);
        float4 h1 = h2f4(T1[(size_t)s1 * 32 + lane]);
        float4 h2 = h2f4(T1[(size_t)s2 * 32 + lane]);
        float4 h3 = h2f4(T1[(size_t)s3 * 32 + lane]);
        acc.x = fmaf(w0,h0.x,acc.x); acc.y = fmaf(w0,h0.y,acc.y);
        acc.z = fmaf(w0,h0.z,acc.z); acc.w = fmaf(w0,h0.w,acc.w);
        acc.x = fmaf(w1,h1.x,acc.x); acc.y = fmaf(w1,h1.y,acc.y);
        acc.z = fmaf(w1,h1.z,acc.z); acc.w = fmaf(w1,h1.w,acc.w);
        acc.x = fmaf(w2,h2.x,acc.x); acc.y = fmaf(w2,h2.y,acc.y);
        acc.z = fmaf(w2,h2.z,acc.z); acc.w = fmaf(w2,h2.w,acc.w);
        acc.x = fmaf(w3,h3.x,acc.x); acc.y = fmaf(w3,h3.y,acc.y);
        acc.z = fmaf(w3,h3.z,acc.z); acc.w = fmaf(w3,h3.w,acc.w);
    }
    for (; e < end; e++) {
        int s = g_ecol[e];
        float w = g_ew[e];
        float4 hv = h2f4(T1[(size_t)s * 32 + lane]);
        acc.x = fmaf(w,hv.x,acc.x); acc.y = fmaf(w,hv.y,acc.y);
        acc.z = fmaf(w,hv.z,acc.z); acc.w = fmaf(w,hv.w,acc.w);
    }
    float4 hd = h2f4(((const uint2*)g_h)[(size_t)warp * 32 + lane]);
    float4 o;
    o.x = 2.f * acc.x - hd.x;
    o.y = 2.f * acc.y - hd.y;
    o.z = 2.f * acc.z - hd.z;
    o.w = 2.f * acc.w - hd.w;
    ((uint2*)g_t2)[(size_t)warp * 32 + lane] = f2h4(o);
}

// ---------------- fused: Dirichlet reg of final h + global mean pool ----------------
__global__ void __launch_bounds__(256) k_regpool(const int* __restrict__ batch) {
    __shared__ float blk_ss[8];
    int warp = blockIdx.x * 8 + (threadIdx.x >> 5);
    int lane = threadIdx.x & 31;
    const uint2* H = (const uint2*)g_h;
    float ss = 0.f;
    if (warp < NN) {
        int beg = g_rowptr[warp], end = g_rowptr[warp + 1];
        float4 hd = h2f4(H[(size_t)warp * 32 + lane]);
        int e = beg;
        for (; e + 4 <= end; e += 4) {
            int s0 = g_ecol[e],   s1 = g_ecol[e+1];
            int s2 = g_ecol[e+2], s3 = g_ecol[e+3];
            float4 h0 = h2f4(H[(size_t)s0 * 32 + lane]);
            float4 h1 = h2f4(H[(size_t)s1 * 32 + lane]);
            float4 h2 = h2f4(H[(size_t)s2 * 32 + lane]);
            float4 h3 = h2f4(H[(size_t)s3 * 32 + lane]);
            float dx, dy, dz, dw;
            dx=h0.x-hd.x; dy=h0.y-hd.y; dz=h0.z-hd.z; dw=h0.w-hd.w;
            ss=fmaf(dx,dx,ss); ss=fmaf(dy,dy,ss); ss=fmaf(dz,dz,ss); ss=fmaf(dw,dw,ss);
            dx=h1.x-hd.x; dy=h1.y-hd.y; dz=h1.z-hd.z; dw=h1.w-hd.w;
            ss=fmaf(dx,dx,ss); ss=fmaf(dy,dy,ss); ss=fmaf(dz,dz,ss); ss=fmaf(dw,dw,ss);
            dx=h2.x-hd.x; dy=h2.y-hd.y; dz=h2.z-hd.z; dw=h2.w-hd.w;
            ss=fmaf(dx,dx,ss); ss=fmaf(dy,dy,ss); ss=fmaf(dz,dz,ss); ss=fmaf(dw,dw,ss);
            dx=h3.x-hd.x; dy=h3.y-hd.y; dz=h3.z-hd.z; dw=h3.w-hd.w;
            ss=fmaf(dx,dx,ss); ss=fmaf(dy,dy,ss); ss=fmaf(dz,dz,ss); ss=fmaf(dw,dw,ss);
        }
        for (; e < end; e++) {
            int s = g_ecol[e];
            float4 hv = h2f4(H[(size_t)s * 32 + lane]);
            float dx=hv.x-hd.x, dy=hv.y-hd.y, dz=hv.z-hd.z, dw=hv.w-hd.w;
            ss=fmaf(dx,dx,ss); ss=fmaf(dy,dy,ss); ss=fmaf(dz,dz,ss); ss=fmaf(dw,dw,ss);
        }
        // pool
        int b = batch[warp];
        float* gp = &g_gsum[(size_t)b * HH + lane * 4];
        atomicAdd(gp + 0, hd.x);
        atomicAdd(gp + 1, hd.y);
        atomicAdd(gp + 2, hd.z);
        atomicAdd(gp + 3, hd.w);
        if (lane == 0) atomicAdd(&g_gcnt[b], 1.f);
    }
    #pragma unroll
    for (int off = 16; off > 0; off >>= 1)
        ss += __shfl_xor_sync(0xffffffffu, ss, off);
    if (lane == 0) blk_ss[threadIdx.x >> 5] = ss;
    __syncthreads();
    if (threadIdx.x == 0) {
        double tot = 0.0;
        #pragma unroll
        for (int j = 0; j < 8; j++) tot += (double)blk_ss[j];
        atomicAdd(&g_reg, tot);
    }
}

// ---------------- BN apply (scale/shift computed once per block in smem; bnfin deleted) ----------------
__global__ void k_bnapply(int l, const float* __restrict__ bng, const float* __restrict__ bnb) {
    __shared__ float scS[HH], shS[HH];
    int tid = threadIdx.x;
    if (tid < HH) {
        float m = g_bnsum[l * HH + tid] * (1.f / NN);
        float v = g_bnsq[l * HH + tid] * (1.f / NN) - m * m;
        float s = bng[tid] * rsqrtf(v + EPSF);
        scS[tid] = s;
        shS[tid] = bnb[tid] - m * s;
    }
    __syncthreads();
    int i = blockIdx.x * blockDim.x + tid;   // uint2 index over NN*32
    int c4 = i & 31;
    float4 v  = h2f4(((const uint2*)g_o)[i]);
    float4 sc = ((const float4*)scS)[c4];
    float4 sh = ((const float4*)shS)[c4];
    float4 o;
    o.x = fmaxf(fmaf(v.x, sc.x, sh.x), 0.f);
    o.y = fmaxf(fmaf(v.y, sc.y, sh.y), 0.f);
    o.z = fmaxf(fmaf(v.z, sc.z, sh.z), 0.f);
    o.w = fmaxf(fmaf(v.w, sc.w, sh.w), 0.f);
    ((uint2*)g_h)[i] = f2h4(o);
}

// ---------------- MLP head + output ----------------
__global__ void k_head(const float* __restrict__ w1, const float* __restrict__ b1,
                       const float* __restrict__ w2, const float* __restrict__ b2,
                       float* __restrict__ out, int out_size)
{
    __shared__ float gm[HH];
    __shared__ float zz[64];
    int g = blockIdx.x, t = threadIdx.x;
    float cnt = fmaxf(g_gcnt[g], 1.f);
    gm[t] = g_gsum[(size_t)g * HH + t] / cnt;
    __syncthreads();
    if (t < 64) {
        float a = b1[t];
        #pragma unroll 4
        for (int c = 0; c < HH; c++) a = fmaf(gm[c], w1[c * 64 + t], a);
        zz[t] = fmaxf(a, 0.f);
    }
    __syncthreads();
    if (t < 2) {
        float a = b2[t];
        #pragma unroll 4
        for (int k = 0; k < 64; k++) a = fmaf(zz[k], w2[k * 2 + t], a);
        out[g * 2 + t] = a;
    }
    if (g == 0 && t == 0 && out_size > 256)
        out[256] = (float)(g_reg / (4.0 * (double)EE));
}

// ---------------- launch ----------------
extern "C" void kernel_launch(void* const* d_in, const int* in_sizes, int n_in,
                              void* d_out, int out_size)
{
    const float* x      = (const float*)d_in[0];
    const float* w_in   = (const float*)d_in[1];
    const float* b_in   = (const float*)d_in[2];
    const float* ln_g   = (const float*)d_in[3];
    const float* ln_b   = (const float*)d_in[4];
    const float* cheb_w = (const float*)d_in[5];
    const float* cheb_b = (const float*)d_in[6];
    const float* bn_g   = (const float*)d_in[7];
    const float* bn_b   = (const float*)d_in[8];
    const float* w1     = (const float*)d_in[9];
    const float* b1     = (const float*)d_in[10];
    const float* w2     = (const float*)d_in[11];
    const float* b2     = (const float*)d_in[12];
    const int* ei       = (const int*)d_in[13];
    const int* batch    = (const int*)d_in[14];
    float* out = (float*)d_out;

    cudaFuncSetAttribute(k_embed_mma, cudaFuncAttributeMaxDynamicSharedMemorySize, SMEM_DYN);
    cudaFuncSetAttribute(k_cheb_mma,  cudaFuncAttributeMaxDynamicSharedMemorySize, SMEM_DYN);

    const int FB = NN * 32 / 256;            // 6250 (uint2 elements / 256)
    const int NODE_WARP_BLKS = (NN + 7) / 8; // 6250

    k_init<<<(NN + 255) / 256, 256>>>();
    k_edge_prep<<<EE / 256, 256>>>(ei);
    k_scan1<<<NBLK, SCAN_B>>>();             // + dinv
    k_scan3<<<NBLK, SCAN_B>>>();             // self-computes block offsets (scan2 deleted)
    k_scatter<<<EE / 256, 256>>>(ei);

    k_embed_mma<<<NTILE, 256, SMEM_DYN>>>(x, w_in, b_in, ln_g, ln_b);

    for (int l = 0; l < LL; l++) {
        k_spmm1<<<NODE_WARP_BLKS, 256>>>();
        k_spmm2<<<NODE_WARP_BLKS, 256>>>();
        k_cheb_mma<<<NTILE, 256, SMEM_DYN>>>(l,
                                             cheb_w + (size_t)l * KK * HH * HH,
                                             cheb_b + (size_t)l * HH);
        k_bnapply<<<FB, 256>>>(l, bn_g + (size_t)l * HH, bn_b + (size_t)l * HH);
    }

    k_regpool<<<NODE_WARP_BLKS, 256>>>(batch);
    k_head<<<GG, HH>>>(w1, b1, w2, b2, out, out_size);
}